// round 1
// baseline (speedup 1.0000x reference)
#include <cuda_runtime.h>
#include <math.h>

#define BQ 4
#define PP 1024
#define DDA 1024
#define DDC 3072
#define HID 512

// ---------------- scratch (static device memory, no allocation) ----------------
__device__ float g_act_cos[(size_t)BQ*PP*PP];
__device__ float g_comp_cos[(size_t)BQ*PP*PP];
__device__ float g_act_adj[(size_t)BQ*PP*PP];
__device__ float g_comp_adj[(size_t)BQ*PP*PP];
__device__ float g_norm_a[BQ*PP];
__device__ float g_norm_c[BQ*PP];
__device__ float g_t1[(size_t)BQ*PP*HID];
__device__ float g_t2[(size_t)BQ*PP*HID];
__device__ float g_t3[(size_t)BQ*PP*DDC];
__device__ float g_of[(size_t)BQ*PP*DDC];

// ---------------- generic tiled SGEMM ----------------
// C[M,N] = A[M,K] @ B[K,N]   (TB=false, B row-major K x N)
// C[M,N] = A[M,K] @ B[N,K]^T (TB=true,  B row-major N x K)
// batched over blockIdx.z with strides; optional bias[N], residual[M,N], relu; ldc output stride.
#define BM 64
#define BN 64
#define BKT 16

template<bool TB>
__global__ __launch_bounds__(256)
void sgemm_k(const float* __restrict__ A, const float* __restrict__ B,
             float* __restrict__ C,
             int M, int N, int K,
             long sA, long sB, long sC,
             const float* __restrict__ bias,
             const float* __restrict__ resid, long sR,
             int ldc, int relu_flag)
{
    __shared__ float As[BKT][BM];
    __shared__ float Bs[BKT][BN];

    long bz = blockIdx.z;
    A += bz * sA;
    B += bz * sB;
    C += bz * sC;
    if (resid) resid += bz * sR;

    int bm = blockIdx.y * BM;
    int bn = blockIdx.x * BN;
    int tid = threadIdx.x;
    int tx = tid & 15;
    int ty = tid >> 4;

    float acc[4][4];
#pragma unroll
    for (int i = 0; i < 4; i++)
#pragma unroll
        for (int j = 0; j < 4; j++) acc[i][j] = 0.f;

    int arow = tid >> 2;          // 0..63
    int acol = (tid & 3) * 4;     // 0,4,8,12

    for (int k0 = 0; k0 < K; k0 += BKT) {
        // A tile: BM x BKT
#pragma unroll
        for (int j = 0; j < 4; j++) {
            int gr = bm + arow, gc = k0 + acol + j;
            As[acol + j][arow] = (gr < M && gc < K) ? A[(size_t)gr * K + gc] : 0.f;
        }
        if (TB) {
            int brow = tid >> 2;          // n 0..63
            int bcol = (tid & 3) * 4;     // k
#pragma unroll
            for (int j = 0; j < 4; j++) {
                int gn = bn + brow, gk = k0 + bcol + j;
                Bs[bcol + j][brow] = (gn < N && gk < K) ? B[(size_t)gn * K + gk] : 0.f;
            }
        } else {
            int brow = tid >> 4;          // k 0..15
            int bcol = (tid & 15) * 4;    // n
#pragma unroll
            for (int j = 0; j < 4; j++) {
                int gk = k0 + brow, gn = bn + bcol + j;
                Bs[brow][bcol + j] = (gk < K && gn < N) ? B[(size_t)gk * N + gn] : 0.f;
            }
        }
        __syncthreads();

#pragma unroll
        for (int kk = 0; kk < BKT; kk++) {
            float4 av = *reinterpret_cast<const float4*>(&As[kk][ty * 4]);
            float4 bv = *reinterpret_cast<const float4*>(&Bs[kk][tx * 4]);
            float a4[4] = {av.x, av.y, av.z, av.w};
            float b4[4] = {bv.x, bv.y, bv.z, bv.w};
#pragma unroll
            for (int i = 0; i < 4; i++)
#pragma unroll
                for (int j = 0; j < 4; j++)
                    acc[i][j] += a4[i] * b4[j];
        }
        __syncthreads();
    }

#pragma unroll
    for (int i = 0; i < 4; i++) {
        int r = bm + ty * 4 + i;
        if (r >= M) continue;
#pragma unroll
        for (int j = 0; j < 4; j++) {
            int c = bn + tx * 4 + j;
            if (c >= N) continue;
            float v = acc[i][j];
            if (bias) v += bias[c];
            if (resid) v += resid[(size_t)r * N + c];
            if (relu_flag) v = fmaxf(v, 0.f);
            C[(size_t)r * ldc + c] = v;
        }
    }
}

// ---------------- norms + cosine normalization ----------------
__global__ void norms_k(const float* __restrict__ G, float* __restrict__ nrm)
{
    int i = blockIdx.x * blockDim.x + threadIdx.x;
    if (i < BQ * PP) {
        int b = i >> 10, p = i & (PP - 1);
        nrm[i] = sqrtf(G[((size_t)b * PP + p) * PP + p]);
    }
}

__global__ void cosnorm_k(float* __restrict__ G, const float* __restrict__ nrm)
{
    size_t total = (size_t)BQ * PP * PP;
    for (size_t idx = (size_t)blockIdx.x * blockDim.x + threadIdx.x; idx < total;
         idx += (size_t)gridDim.x * blockDim.x) {
        int q = (int)(idx & (PP - 1));
        size_t r = idx >> 10;       // b*P + p
        int b = (int)(r >> 10);
        float np = nrm[r];
        float nq = nrm[((size_t)b << 10) + q];
        G[idx] = G[idx] / (np * nq + 1e-6f);
    }
}

// ---------------- graph construction (one warp per row) ----------------
__device__ __forceinline__ void warp_argmin(float& v, int& l)
{
#pragma unroll
    for (int off = 16; off; off >>= 1) {
        float ov = __shfl_down_sync(0xffffffffu, v, off);
        int ol = __shfl_down_sync(0xffffffffu, l, off);
        if (ov < v) { v = ov; l = ol; }
    }
    v = __shfl_sync(0xffffffffu, v, 0);
    l = __shfl_sync(0xffffffffu, l, 0);
}

__device__ __forceinline__ void warp_argmax(float& v, int& l)
{
#pragma unroll
    for (int off = 16; off; off >>= 1) {
        float ov = __shfl_down_sync(0xffffffffu, v, off);
        int ol = __shfl_down_sync(0xffffffffu, l, off);
        if (ov > v) { v = ov; l = ol; }
    }
    v = __shfl_sync(0xffffffffu, v, 0);
    l = __shfl_sync(0xffffffffu, l, 0);
}

__global__ __launch_bounds__(128)
void build_adj_k(const float* __restrict__ iou, const float* __restrict__ dis,
                 const float* __restrict__ acos_, const float* __restrict__ ccos_,
                 const int* __restrict__ props,
                 float* __restrict__ aadj, float* __restrict__ cadj)
{
    int warp = threadIdx.x >> 5, lane = threadIdx.x & 31;
    int row = blockIdx.x * (blockDim.x >> 5) + warp;
    if (row >= BQ * PP) return;
    int b = row >> 10;
    int p = row & (PP - 1);
    const float* iour = iou + (size_t)row * PP;
    const float* disr = dis + (size_t)row * PP;
    const float* ar = acos_ + (size_t)row * PP;
    const float* cr = ccos_ + (size_t)row * PP;
    int pn = props[b];
    bool pv = p < pn;

    // per-lane top-6 smallest dis_m, top-2 largest sem_m (sentinels included, like jax)
    float dv[6]; int di[6];
#pragma unroll
    for (int j = 0; j < 6; j++) { dv[j] = 3.0e38f; di[j] = -1; }
    float sv[2] = {-3.0e38f, -3.0e38f};
    int si[2] = {-1, -1};

    for (int q = lane; q < PP; q += 32) {
        float io = iour[q];
        bool ip = io > 0.0f;
        bool qv = q < pn;
        bool v2 = pv && qv;

        float dm = v2 ? (ip ? 2.0f : disr[q]) : 1.0e9f;
        if (dm < dv[5]) {
            dv[5] = dm; di[5] = q;
#pragma unroll
            for (int j = 5; j > 0; j--) {
                if (dv[j] < dv[j - 1]) {
                    float tv = dv[j]; dv[j] = dv[j - 1]; dv[j - 1] = tv;
                    int ti = di[j]; di[j] = di[j - 1]; di[j - 1] = ti;
                }
            }
        }
        float sm = v2 ? (ip ? 0.0f : (ar[q] - (q == p ? 1.0f : 0.0f))) : -1.0e9f;
        if (sm > sv[1]) {
            if (sm > sv[0]) { sv[1] = sv[0]; si[1] = si[0]; sv[0] = sm; si[0] = q; }
            else            { sv[1] = sm; si[1] = q; }
        }
    }

    int sel[8];
    {
        int ptr = 0;
        for (int k = 0; k < 6; k++) {
            float cv = (ptr < 6) ? dv[ptr] : 3.0e38f;
            int ci = (ptr < 6) ? di[ptr] : -1;
            float v = cv; int l = lane;
            warp_argmin(v, l);
            sel[k] = __shfl_sync(0xffffffffu, ci, l);
            if (lane == l) ptr++;
        }
    }
    {
        int ptr = 0;
        for (int k = 0; k < 2; k++) {
            float cv = (ptr < 2) ? sv[ptr] : -3.0e38f;
            int ci = (ptr < 2) ? si[ptr] : -1;
            float v = cv; int l = lane;
            warp_argmax(v, l);
            sel[6 + k] = __shfl_sync(0xffffffffu, ci, l);
            if (lane == l) ptr++;
        }
    }
    // filter selections: keep only (not iou_pos) && valid pair
#pragma unroll
    for (int k = 0; k < 8; k++) {
        int q = sel[k];
        bool ok = (q >= 0) && pv && (q < pn) && !(iour[q] > 0.0f);
        sel[k] = ok ? q : -1;
    }

    // pass 2: mask bits + count
    unsigned mbits = 0;
    for (int i = 0; i < 32; i++) {
        int q = lane + 32 * i;
        float io = iour[q];
        bool bit = (q != p) && (io > 0.7f);   // iou_adj = iou - eye > 0.7
#pragma unroll
        for (int k = 0; k < 8; k++) bit |= (sel[k] == q);
        mbits |= (bit ? 1u : 0u) << i;
    }
    int cnt = __popc(mbits);
#pragma unroll
    for (int off = 16; off; off >>= 1) cnt += __shfl_xor_sync(0xffffffffu, cnt, off);
    float inv = 1.0f / ((float)cnt + 1e-6f);

    // pass 3: write adjacencies = relu(cos * (bit*inv + eye))
    float* aw = aadj + (size_t)row * PP;
    float* cw = cadj + (size_t)row * PP;
    for (int i = 0; i < 32; i++) {
        int q = lane + 32 * i;
        float m = ((mbits >> i) & 1u) ? inv : 0.0f;
        if (q == p) m += 1.0f;
        float a = ar[q] * m;
        float c = cr[q] * m;
        aw[q] = a > 0.f ? a : 0.f;
        cw[q] = c > 0.f ? c : 0.f;
    }
}

// ---------------- host orchestration ----------------
static void launch_sgemm(bool tb, const float* A, const float* B, float* C,
                         int M, int N, int K,
                         long sA, long sB, long sC, int batch,
                         const float* bias, const float* resid, long sR,
                         int ldc, int relu)
{
    dim3 grid((N + BN - 1) / BN, (M + BM - 1) / BM, batch);
    if (tb)
        sgemm_k<true><<<grid, 256>>>(A, B, C, M, N, K, sA, sB, sC, bias, resid, sR, ldc, relu);
    else
        sgemm_k<false><<<grid, 256>>>(A, B, C, M, N, K, sA, sB, sC, bias, resid, sR, ldc, relu);
}

extern "C" void kernel_launch(void* const* d_in, const int* in_sizes, int n_in,
                              void* d_out, int out_size)
{
    const float* act   = (const float*)d_in[0];
    const float* comp  = (const float*)d_in[1];
    const float* iou   = (const float*)d_in[2];
    const float* dis   = (const float*)d_in[3];
    const int*   props = (const int*)d_in[4];
    const float* a_w1  = (const float*)d_in[5];
    const float* a_b1  = (const float*)d_in[6];
    const float* a_w2  = (const float*)d_in[7];
    const float* a_b2  = (const float*)d_in[8];
    const float* c_w1  = (const float*)d_in[9];
    const float* c_b1  = (const float*)d_in[10];
    const float* c_w2  = (const float*)d_in[11];
    const float* c_b2  = (const float*)d_in[12];
    const float* fa_w  = (const float*)d_in[13];
    const float* fa_b  = (const float*)d_in[14];
    const float* fc_w  = (const float*)d_in[15];
    const float* fc_b  = (const float*)d_in[16];
    const float* fr_w  = (const float*)d_in[17];
    const float* fr_b  = (const float*)d_in[18];
    float* out = (float*)d_out;

    float *acos_, *ccos_, *aadj, *cadj, *t1, *t2, *t3, *of, *na, *nc;
    cudaGetSymbolAddress((void**)&acos_, g_act_cos);
    cudaGetSymbolAddress((void**)&ccos_, g_comp_cos);
    cudaGetSymbolAddress((void**)&aadj,  g_act_adj);
    cudaGetSymbolAddress((void**)&cadj,  g_comp_adj);
    cudaGetSymbolAddress((void**)&t1,    g_t1);
    cudaGetSymbolAddress((void**)&t2,    g_t2);
    cudaGetSymbolAddress((void**)&t3,    g_t3);
    cudaGetSymbolAddress((void**)&of,    g_of);
    cudaGetSymbolAddress((void**)&na,    g_norm_a);
    cudaGetSymbolAddress((void**)&nc,    g_norm_c);

    // 1) Gram matrices (A @ A^T per batch)
    launch_sgemm(true, act, act, acos_, PP, PP, DDA,
                 (long)PP * DDA, (long)PP * DDA, (long)PP * PP, BQ,
                 nullptr, nullptr, 0, PP, 0);
    launch_sgemm(true, comp, comp, ccos_, PP, PP, DDC,
                 (long)PP * DDC, (long)PP * DDC, (long)PP * PP, BQ,
                 nullptr, nullptr, 0, PP, 0);

    // 2) cosine normalization
    norms_k<<<(BQ * PP + 255) / 256, 256>>>(acos_, na);
    norms_k<<<(BQ * PP + 255) / 256, 256>>>(ccos_, nc);
    cosnorm_k<<<4096, 256>>>(acos_, na);
    cosnorm_k<<<4096, 256>>>(ccos_, nc);

    // 3) graph construction -> act_adj, comp_adj
    build_adj_k<<<(BQ * PP) / 4, 128>>>(iou, dis, acos_, ccos_, props, aadj, cadj);

    // 4) Act GCN:  out = adj@(relu(adj@(x@w1)+b1)@w2) + b2 + x
    launch_sgemm(false, act, a_w1, t1, BQ * PP, HID, DDA, 0, 0, 0, 1,
                 nullptr, nullptr, 0, HID, 0);
    launch_sgemm(false, aadj, t1, t2, PP, HID, PP,
                 (long)PP * PP, (long)PP * HID, (long)PP * HID, BQ,
                 a_b1, nullptr, 0, HID, 1);
    launch_sgemm(false, t2, a_w2, t3, BQ * PP, DDA, HID, 0, 0, 0, 1,
                 nullptr, nullptr, 0, DDA, 0);
    launch_sgemm(false, aadj, t3, of, PP, DDA, PP,
                 (long)PP * PP, (long)PP * DDA, (long)PP * DDA, BQ,
                 a_b2, act, (long)PP * DDA, DDA, 0);
    // head 1: out[:, 0:21]
    launch_sgemm(false, of, fa_w, out, BQ * PP, 21, DDA, 0, 0, 0, 1,
                 fa_b, nullptr, 0, 81, 0);

    // 5) Comp GCN
    launch_sgemm(false, comp, c_w1, t1, BQ * PP, HID, DDC, 0, 0, 0, 1,
                 nullptr, nullptr, 0, HID, 0);
    launch_sgemm(false, cadj, t1, t2, PP, HID, PP,
                 (long)PP * PP, (long)PP * HID, (long)PP * HID, BQ,
                 c_b1, nullptr, 0, HID, 1);
    launch_sgemm(false, t2, c_w2, t3, BQ * PP, DDC, HID, 0, 0, 0, 1,
                 nullptr, nullptr, 0, DDC, 0);
    launch_sgemm(false, cadj, t3, of, PP, DDC, PP,
                 (long)PP * PP, (long)PP * DDC, (long)PP * DDC, BQ,
                 c_b2, comp, (long)PP * DDC, DDC, 0);
    // head 2: out[:, 21:41], head 3: out[:, 41:81]
    launch_sgemm(false, of, fc_w, out + 21, BQ * PP, 20, DDC, 0, 0, 0, 1,
                 fc_b, nullptr, 0, 81, 0);
    launch_sgemm(false, of, fr_w, out + 41, BQ * PP, 40, DDC, 0, 0, 0, 1,
                 fr_b, nullptr, 0, 81, 0);
}

// round 3
// speedup vs baseline: 3.0271x; 3.0271x over previous
#include <cuda_runtime.h>
#include <math.h>
#include <stdint.h>

#define BQ 4
#define PP 1024
#define DDA 1024
#define DDC 3072
#define HID 512

// ---------------- scratch (static device memory, no allocation) ----------------
__device__ float g_act_cos[(size_t)BQ*PP*PP];
__device__ float g_comp_cos[(size_t)BQ*PP*PP];
__device__ float g_act_adj[(size_t)BQ*PP*PP];
__device__ float g_comp_adj[(size_t)BQ*PP*PP];
__device__ float g_norm_a[BQ*PP];
__device__ float g_norm_c[BQ*PP];
__device__ float g_t1[(size_t)BQ*PP*HID];
__device__ float g_t2[(size_t)BQ*PP*HID];
__device__ float g_t3[(size_t)BQ*PP*DDC];
__device__ float g_of[(size_t)BQ*PP*DDC];

// ====================== low-level helpers ======================
__device__ __forceinline__ uint32_t smem_u32(const void* p) {
    uint32_t a;
    asm("{ .reg .u64 t; cvta.to.shared.u64 t, %1; cvt.u32.u64 %0, t; }" : "=r"(a) : "l"(p));
    return a;
}
__device__ __forceinline__ uint32_t pack_bf16x2(float lo_e, float hi_e) {
    // low16 = bf16(lo_e), high16 = bf16(hi_e)
    uint32_t r;
    asm("cvt.rn.bf16x2.f32 %0, %1, %2;" : "=r"(r) : "f"(hi_e), "f"(lo_e));
    return r;
}
__device__ __forceinline__ void ldmx4(uint32_t* r, uint32_t addr) {
    asm volatile("ldmatrix.sync.aligned.m8n8.x4.shared.b16 {%0,%1,%2,%3}, [%4];"
                 : "=r"(r[0]), "=r"(r[1]), "=r"(r[2]), "=r"(r[3]) : "r"(addr));
}
__device__ __forceinline__ void ldmx2(uint32_t* r, uint32_t addr) {
    asm volatile("ldmatrix.sync.aligned.m8n8.x2.shared.b16 {%0,%1}, [%2];"
                 : "=r"(r[0]), "=r"(r[1]) : "r"(addr));
}
__device__ __forceinline__ void mma_bf16(float* c, const uint32_t* a, const uint32_t* b) {
    asm volatile(
        "mma.sync.aligned.m16n8k16.row.col.f32.bf16.bf16.f32 "
        "{%0,%1,%2,%3}, {%4,%5,%6,%7}, {%8,%9}, {%0,%1,%2,%3};"
        : "+f"(c[0]), "+f"(c[1]), "+f"(c[2]), "+f"(c[3])
        : "r"(a[0]), "r"(a[1]), "r"(a[2]), "r"(a[3]), "r"(b[0]), "r"(b[1]));
}
__device__ __forceinline__ void split_pack(float4 v, uint2& hi, uint2& lo) {
    uint32_t ux = __float_as_uint(v.x), uy = __float_as_uint(v.y);
    uint32_t uz = __float_as_uint(v.z), uw = __float_as_uint(v.w);
    hi.x = __byte_perm(ux, uy, 0x7632);
    hi.y = __byte_perm(uz, uw, 0x7632);
    float lx = v.x - __uint_as_float(ux & 0xFFFF0000u);
    float ly = v.y - __uint_as_float(uy & 0xFFFF0000u);
    float lz = v.z - __uint_as_float(uz & 0xFFFF0000u);
    float lw = v.w - __uint_as_float(uw & 0xFFFF0000u);
    lo.x = pack_bf16x2(lx, ly);
    lo.y = pack_bf16x2(lz, lw);
}

// ====================== bf16x3 mma.sync GEMM ======================
// C[M,N] (+bias,+resid,relu) = A[M,K] @ B
// TBK=1 : B stored [N,K] row-major (K-major)  -> Gram A@A^T
// TBK=0 : B stored [K,N] row-major            -> transposed load
// M,N % 128 == 0, K % 32 == 0 required.
#define KSTEP 32
#define ROWB 80                 // bytes per SMEM row (40 bf16, pad for ldmatrix)
#define TILE_B (128*ROWB)       // 10240 bytes per (operand, hl) tile
#define GDSMEM (8*TILE_B)       // 81920: A hi/lo x2 stages + B hi/lo x2 stages

template<int TBK>
__global__ __launch_bounds__(256, 1)
void gemmt_k(const float* __restrict__ A, const float* __restrict__ B,
             float* __restrict__ C, int M, int N, int K,
             long sA, long sB, long sC,
             const float* __restrict__ bias,
             const float* __restrict__ resid, long sR,
             int ldc, int relu_flag)
{
    extern __shared__ char sm[];
    uint32_t smb = smem_u32(sm);

    const int tid = threadIdx.x;
    const int lane = tid & 31;
    const int wid = tid >> 5;
    const int wm = (wid >> 2) * 64;   // warp m offset (0/64)
    const int wn = (wid & 3) * 32;    // warp n offset (0..96)

    long bz = blockIdx.z;
    const int bm = blockIdx.y * 128;
    const int bn = blockIdx.x * 128;
    const float* Ab = A + bz * sA + (size_t)bm * K;
    const float* Bb = B + bz * sB;
    float* Cb = C + bz * sC;
    const float* Rb = resid ? resid + bz * sR : (const float*)0;
    const float* Bblk = TBK ? (Bb + (size_t)bn * K) : (Bb + bn);

    float acc[4][4][4];
#pragma unroll
    for (int i = 0; i < 4; i++)
#pragma unroll
        for (int j = 0; j < 4; j++)
#pragma unroll
            for (int r = 0; r < 4; r++) acc[i][j][r] = 0.f;

    const int nch = K / KSTEP;

    // staging registers
    float4 ra[4];
    float4 rb[4];

    // ---- loader lambdas (manual) ----
    const int a_row = tid >> 3;          // idx>>3 base per it handled below
    const int a_c4 = (tid & 7) << 2;

    // prologue: LDG chunk 0
#pragma unroll
    for (int it = 0; it < 4; it++) {
        int row = it * 32 + a_row;
        ra[it] = *reinterpret_cast<const float4*>(Ab + (size_t)row * K + a_c4);
    }
    if (TBK) {
#pragma unroll
        for (int it = 0; it < 4; it++) {
            int row = it * 32 + a_row;
            rb[it] = *reinterpret_cast<const float4*>(Bblk + (size_t)row * K + a_c4);
        }
    } else {
        int kb = (tid >> 5) << 2, nb = (tid & 31) << 2;
#pragma unroll
        for (int r = 0; r < 4; r++)
            rb[r] = *reinterpret_cast<const float4*>(Bblk + (size_t)(kb + r) * N + nb);
    }

    // STS chunk 0 into stage 0
    {
        char* ahP = sm;               // stage0 A hi
        char* alP = sm + TILE_B;      // stage0 A lo
        char* bhP = sm + 4 * TILE_B;  // stage0 B hi
        char* blP = sm + 5 * TILE_B;
#pragma unroll
        for (int it = 0; it < 4; it++) {
            int row = it * 32 + a_row;
            uint2 h, l;
            split_pack(ra[it], h, l);
            *reinterpret_cast<uint2*>(ahP + row * ROWB + a_c4 * 2) = h;
            *reinterpret_cast<uint2*>(alP + row * ROWB + a_c4 * 2) = l;
        }
        if (TBK) {
#pragma unroll
            for (int it = 0; it < 4; it++) {
                int row = it * 32 + a_row;
                uint2 h, l;
                split_pack(rb[it], h, l);
                *reinterpret_cast<uint2*>(bhP + row * ROWB + a_c4 * 2) = h;
                *reinterpret_cast<uint2*>(blP + row * ROWB + a_c4 * 2) = l;
            }
        } else {
            int kb = (tid >> 5) << 2, nb = (tid & 31) << 2;
            float e[4][4];
            *reinterpret_cast<float4*>(e[0]) = rb[0];
            *reinterpret_cast<float4*>(e[1]) = rb[1];
            *reinterpret_cast<float4*>(e[2]) = rb[2];
            *reinterpret_cast<float4*>(e[3]) = rb[3];
#pragma unroll
            for (int j = 0; j < 4; j++) {
                uint32_t u0 = __float_as_uint(e[0][j]), u1 = __float_as_uint(e[1][j]);
                uint32_t u2 = __float_as_uint(e[2][j]), u3 = __float_as_uint(e[3][j]);
                uint2 h, l;
                h.x = __byte_perm(u0, u1, 0x7632);
                h.y = __byte_perm(u2, u3, 0x7632);
                float l0 = e[0][j] - __uint_as_float(u0 & 0xFFFF0000u);
                float l1 = e[1][j] - __uint_as_float(u1 & 0xFFFF0000u);
                float l2 = e[2][j] - __uint_as_float(u2 & 0xFFFF0000u);
                float l3 = e[3][j] - __uint_as_float(u3 & 0xFFFF0000u);
                l.x = pack_bf16x2(l0, l1);
                l.y = pack_bf16x2(l2, l3);
                *reinterpret_cast<uint2*>(bhP + (nb + j) * ROWB + kb * 2) = h;
                *reinterpret_cast<uint2*>(blP + (nb + j) * ROWB + kb * 2) = l;
            }
        }
    }
    __syncthreads();

    for (int kt = 0; kt < nch; kt++) {
        int s = kt & 1;
        // LDG next chunk (overlaps with mma below via scoreboard)
        if (kt + 1 < nch) {
            int k0 = (kt + 1) * KSTEP;
#pragma unroll
            for (int it = 0; it < 4; it++) {
                int row = it * 32 + a_row;
                ra[it] = *reinterpret_cast<const float4*>(Ab + (size_t)row * K + k0 + a_c4);
            }
            if (TBK) {
#pragma unroll
                for (int it = 0; it < 4; it++) {
                    int row = it * 32 + a_row;
                    rb[it] = *reinterpret_cast<const float4*>(Bblk + (size_t)row * K + k0 + a_c4);
                }
            } else {
                int kb = (tid >> 5) << 2, nb = (tid & 31) << 2;
#pragma unroll
                for (int r = 0; r < 4; r++)
                    rb[r] = *reinterpret_cast<const float4*>(Bblk + (size_t)(k0 + kb + r) * N + nb);
            }
        }

        // ---- compute stage s ----
        {
            uint32_t aHi = smb + (uint32_t)(s * 2 + 0) * TILE_B;
            uint32_t aLo = smb + (uint32_t)(s * 2 + 1) * TILE_B;
            uint32_t bHi = smb + (uint32_t)(4 + s * 2 + 0) * TILE_B;
            uint32_t bLo = smb + (uint32_t)(4 + s * 2 + 1) * TILE_B;

#pragma unroll
            for (int kh = 0; kh < 2; kh++) {
                int k16 = kh * 16;
                uint32_t ahi[4][4], alo[4][4], bhi[4][2], blo[4][2];
                int arow = wm + (lane & 15);
                uint32_t aoff = (uint32_t)((k16 + ((lane >> 4) << 3)) * 2);
#pragma unroll
                for (int i = 0; i < 4; i++) {
                    uint32_t rowoff = (uint32_t)(arow + i * 16) * ROWB + aoff;
                    ldmx4(ahi[i], aHi + rowoff);
                    ldmx4(alo[i], aLo + rowoff);
                }
                int brow = wn + (lane & 7);
                uint32_t boff = (uint32_t)((k16 + ((lane >> 3) & 1) * 8) * 2);
#pragma unroll
                for (int j = 0; j < 4; j++) {
                    uint32_t rowoff = (uint32_t)(brow + j * 8) * ROWB + boff;
                    ldmx2(bhi[j], bHi + rowoff);
                    ldmx2(blo[j], bLo + rowoff);
                }
#pragma unroll
                for (int i = 0; i < 4; i++)
#pragma unroll
                    for (int j = 0; j < 4; j++)
                        mma_bf16(acc[i][j], ahi[i], bhi[j]);
#pragma unroll
                for (int i = 0; i < 4; i++)
#pragma unroll
                    for (int j = 0; j < 4; j++)
                        mma_bf16(acc[i][j], ahi[i], blo[j]);
#pragma unroll
                for (int i = 0; i < 4; i++)
#pragma unroll
                    for (int j = 0; j < 4; j++)
                        mma_bf16(acc[i][j], alo[i], bhi[j]);
            }
        }

        // ---- STS next chunk into stage s^1 ----
        if (kt + 1 < nch) {
            int s2 = s ^ 1;
            char* ahP = sm + (s2 * 2 + 0) * TILE_B;
            char* alP = sm + (s2 * 2 + 1) * TILE_B;
            char* bhP = sm + (4 + s2 * 2 + 0) * TILE_B;
            char* blP = sm + (4 + s2 * 2 + 1) * TILE_B;
#pragma unroll
            for (int it = 0; it < 4; it++) {
                int row = it * 32 + a_row;
                uint2 h, l;
                split_pack(ra[it], h, l);
                *reinterpret_cast<uint2*>(ahP + row * ROWB + a_c4 * 2) = h;
                *reinterpret_cast<uint2*>(alP + row * ROWB + a_c4 * 2) = l;
            }
            if (TBK) {
#pragma unroll
                for (int it = 0; it < 4; it++) {
                    int row = it * 32 + a_row;
                    uint2 h, l;
                    split_pack(rb[it], h, l);
                    *reinterpret_cast<uint2*>(bhP + row * ROWB + a_c4 * 2) = h;
                    *reinterpret_cast<uint2*>(blP + row * ROWB + a_c4 * 2) = l;
                }
            } else {
                int kb = (tid >> 5) << 2, nb = (tid & 31) << 2;
                float e[4][4];
                *reinterpret_cast<float4*>(e[0]) = rb[0];
                *reinterpret_cast<float4*>(e[1]) = rb[1];
                *reinterpret_cast<float4*>(e[2]) = rb[2];
                *reinterpret_cast<float4*>(e[3]) = rb[3];
#pragma unroll
                for (int j = 0; j < 4; j++) {
                    uint32_t u0 = __float_as_uint(e[0][j]), u1 = __float_as_uint(e[1][j]);
                    uint32_t u2 = __float_as_uint(e[2][j]), u3 = __float_as_uint(e[3][j]);
                    uint2 h, l;
                    h.x = __byte_perm(u0, u1, 0x7632);
                    h.y = __byte_perm(u2, u3, 0x7632);
                    float l0 = e[0][j] - __uint_as_float(u0 & 0xFFFF0000u);
                    float l1 = e[1][j] - __uint_as_float(u1 & 0xFFFF0000u);
                    float l2 = e[2][j] - __uint_as_float(u2 & 0xFFFF0000u);
                    float l3 = e[3][j] - __uint_as_float(u3 & 0xFFFF0000u);
                    l.x = pack_bf16x2(l0, l1);
                    l.y = pack_bf16x2(l2, l3);
                    *reinterpret_cast<uint2*>(bhP + (nb + j) * ROWB + kb * 2) = h;
                    *reinterpret_cast<uint2*>(blP + (nb + j) * ROWB + kb * 2) = l;
                }
            }
        }
        __syncthreads();
    }

    // ---- epilogue: direct register stores with fused bias/resid/relu ----
#pragma unroll
    for (int i = 0; i < 4; i++) {
        int r0 = bm + wm + i * 16 + (lane >> 2);
        int r1 = r0 + 8;
#pragma unroll
        for (int j = 0; j < 4; j++) {
            int col = bn + wn + j * 8 + (lane & 3) * 2;
            float2 v0 = make_float2(acc[i][j][0], acc[i][j][1]);
            float2 v1 = make_float2(acc[i][j][2], acc[i][j][3]);
            if (bias) {
                float2 bv = *reinterpret_cast<const float2*>(bias + col);
                v0.x += bv.x; v0.y += bv.y;
                v1.x += bv.x; v1.y += bv.y;
            }
            if (Rb) {
                float2 q0 = *reinterpret_cast<const float2*>(Rb + (size_t)r0 * N + col);
                float2 q1 = *reinterpret_cast<const float2*>(Rb + (size_t)r1 * N + col);
                v0.x += q0.x; v0.y += q0.y;
                v1.x += q1.x; v1.y += q1.y;
            }
            if (relu_flag) {
                v0.x = fmaxf(v0.x, 0.f); v0.y = fmaxf(v0.y, 0.f);
                v1.x = fmaxf(v1.x, 0.f); v1.y = fmaxf(v1.y, 0.f);
            }
            *reinterpret_cast<float2*>(Cb + (size_t)r0 * ldc + col) = v0;
            *reinterpret_cast<float2*>(Cb + (size_t)r1 * ldc + col) = v1;
        }
    }
}

// ====================== SIMT SGEMM (small-N heads only) ======================
#define BM 64
#define BN 64
#define BKT 16

__global__ __launch_bounds__(256)
void sgemm_k(const float* __restrict__ A, const float* __restrict__ B,
             float* __restrict__ C,
             int M, int N, int K,
             const float* __restrict__ bias, int ldc)
{
    __shared__ float As[BKT][BM];
    __shared__ float Bs[BKT][BN];

    int bm = blockIdx.y * BM;
    int bn = blockIdx.x * BN;
    int tid = threadIdx.x;
    int tx = tid & 15;
    int ty = tid >> 4;

    float acc[4][4];
#pragma unroll
    for (int i = 0; i < 4; i++)
#pragma unroll
        for (int j = 0; j < 4; j++) acc[i][j] = 0.f;

    int arow = tid >> 2;
    int acol = (tid & 3) * 4;

    for (int k0 = 0; k0 < K; k0 += BKT) {
#pragma unroll
        for (int j = 0; j < 4; j++) {
            int gr = bm + arow, gc = k0 + acol + j;
            As[acol + j][arow] = (gr < M && gc < K) ? A[(size_t)gr * K + gc] : 0.f;
        }
        int brow = tid >> 4;
        int bcol = (tid & 15) * 4;
#pragma unroll
        for (int j = 0; j < 4; j++) {
            int gk = k0 + brow, gn = bn + bcol + j;
            Bs[brow][bcol + j] = (gk < K && gn < N) ? B[(size_t)gk * N + gn] : 0.f;
        }
        __syncthreads();
#pragma unroll
        for (int kk = 0; kk < BKT; kk++) {
            float4 av = *reinterpret_cast<const float4*>(&As[kk][ty * 4]);
            float4 bv = *reinterpret_cast<const float4*>(&Bs[kk][tx * 4]);
            float a4[4] = {av.x, av.y, av.z, av.w};
            float b4[4] = {bv.x, bv.y, bv.z, bv.w};
#pragma unroll
            for (int i = 0; i < 4; i++)
#pragma unroll
                for (int j = 0; j < 4; j++)
                    acc[i][j] += a4[i] * b4[j];
        }
        __syncthreads();
    }

#pragma unroll
    for (int i = 0; i < 4; i++) {
        int r = bm + ty * 4 + i;
        if (r >= M) continue;
#pragma unroll
        for (int j = 0; j < 4; j++) {
            int c = bn + tx * 4 + j;
            if (c >= N) continue;
            float v = acc[i][j];
            if (bias) v += bias[c];
            C[(size_t)r * ldc + c] = v;
        }
    }
}

// ---------------- norms + cosine normalization ----------------
__global__ void norms_k(const float* __restrict__ G, float* __restrict__ nrm)
{
    int i = blockIdx.x * blockDim.x + threadIdx.x;
    if (i < BQ * PP) {
        int b = i >> 10, p = i & (PP - 1);
        nrm[i] = sqrtf(G[((size_t)b * PP + p) * PP + p]);
    }
}

__global__ void cosnorm_k(float* __restrict__ G, const float* __restrict__ nrm)
{
    size_t total = (size_t)BQ * PP * PP;
    for (size_t idx = (size_t)blockIdx.x * blockDim.x + threadIdx.x; idx < total;
         idx += (size_t)gridDim.x * blockDim.x) {
        int q = (int)(idx & (PP - 1));
        size_t r = idx >> 10;
        int b = (int)(r >> 10);
        float np = nrm[r];
        float nq = nrm[((size_t)b << 10) + q];
        G[idx] = G[idx] / (np * nq + 1e-6f);
    }
}

// ---------------- graph construction (one warp per row) ----------------
__device__ __forceinline__ void warp_argmin(float& v, int& l)
{
#pragma unroll
    for (int off = 16; off; off >>= 1) {
        float ov = __shfl_down_sync(0xffffffffu, v, off);
        int ol = __shfl_down_sync(0xffffffffu, l, off);
        if (ov < v) { v = ov; l = ol; }
    }
    v = __shfl_sync(0xffffffffu, v, 0);
    l = __shfl_sync(0xffffffffu, l, 0);
}

__device__ __forceinline__ void warp_argmax(float& v, int& l)
{
#pragma unroll
    for (int off = 16; off; off >>= 1) {
        float ov = __shfl_down_sync(0xffffffffu, v, off);
        int ol = __shfl_down_sync(0xffffffffu, l, off);
        if (ov > v) { v = ov; l = ol; }
    }
    v = __shfl_sync(0xffffffffu, v, 0);
    l = __shfl_sync(0xffffffffu, l, 0);
}

__global__ __launch_bounds__(128)
void build_adj_k(const float* __restrict__ iou, const float* __restrict__ dis,
                 const float* __restrict__ acos_, const float* __restrict__ ccos_,
                 const int* __restrict__ props,
                 float* __restrict__ aadj, float* __restrict__ cadj)
{
    int warp = threadIdx.x >> 5, lane = threadIdx.x & 31;
    int row = blockIdx.x * (blockDim.x >> 5) + warp;
    if (row >= BQ * PP) return;
    int b = row >> 10;
    int p = row & (PP - 1);
    const float* iour = iou + (size_t)row * PP;
    const float* disr = dis + (size_t)row * PP;
    const float* ar = acos_ + (size_t)row * PP;
    const float* cr = ccos_ + (size_t)row * PP;
    int pn = props[b];
    bool pv = p < pn;

    float dv[6]; int di[6];
#pragma unroll
    for (int j = 0; j < 6; j++) { dv[j] = 3.0e38f; di[j] = -1; }
    float sv[2] = {-3.0e38f, -3.0e38f};
    int si[2] = {-1, -1};

    for (int q = lane; q < PP; q += 32) {
        float io = iour[q];
        bool ip = io > 0.0f;
        bool qv = q < pn;
        bool v2 = pv && qv;

        float dm = v2 ? (ip ? 2.0f : disr[q]) : 1.0e9f;
        if (dm < dv[5]) {
            dv[5] = dm; di[5] = q;
#pragma unroll
            for (int j = 5; j > 0; j--) {
                if (dv[j] < dv[j - 1]) {
                    float tv = dv[j]; dv[j] = dv[j - 1]; dv[j - 1] = tv;
                    int ti = di[j]; di[j] = di[j - 1]; di[j - 1] = ti;
                }
            }
        }
        float sm = v2 ? (ip ? 0.0f : (ar[q] - (q == p ? 1.0f : 0.0f))) : -1.0e9f;
        if (sm > sv[1]) {
            if (sm > sv[0]) { sv[1] = sv[0]; si[1] = si[0]; sv[0] = sm; si[0] = q; }
            else            { sv[1] = sm; si[1] = q; }
        }
    }

    int sel[8];
    {
        int ptr = 0;
        for (int k = 0; k < 6; k++) {
            float cv = (ptr < 6) ? dv[ptr] : 3.0e38f;
            int ci = (ptr < 6) ? di[ptr] : -1;
            float v = cv; int l = lane;
            warp_argmin(v, l);
            sel[k] = __shfl_sync(0xffffffffu, ci, l);
            if (lane == l) ptr++;
        }
    }
    {
        int ptr = 0;
        for (int k = 0; k < 2; k++) {
            float cv = (ptr < 2) ? sv[ptr] : -3.0e38f;
            int ci = (ptr < 2) ? si[ptr] : -1;
            float v = cv; int l = lane;
            warp_argmax(v, l);
            sel[6 + k] = __shfl_sync(0xffffffffu, ci, l);
            if (lane == l) ptr++;
        }
    }
#pragma unroll
    for (int k = 0; k < 8; k++) {
        int q = sel[k];
        bool ok = (q >= 0) && pv && (q < pn) && !(iour[q] > 0.0f);
        sel[k] = ok ? q : -1;
    }

    unsigned mbits = 0;
    for (int i = 0; i < 32; i++) {
        int q = lane + 32 * i;
        float io = iour[q];
        bool bit = (q != p) && (io > 0.7f);
#pragma unroll
        for (int k = 0; k < 8; k++) bit |= (sel[k] == q);
        mbits |= (bit ? 1u : 0u) << i;
    }
    int cnt = __popc(mbits);
#pragma unroll
    for (int off = 16; off; off >>= 1) cnt += __shfl_xor_sync(0xffffffffu, cnt, off);
    float inv = 1.0f / ((float)cnt + 1e-6f);

    float* aw = aadj + (size_t)row * PP;
    float* cw = cadj + (size_t)row * PP;
    for (int i = 0; i < 32; i++) {
        int q = lane + 32 * i;
        float m = ((mbits >> i) & 1u) ? inv : 0.0f;
        if (q == p) m += 1.0f;
        float a = ar[q] * m;
        float c = cr[q] * m;
        aw[q] = a > 0.f ? a : 0.f;
        cw[q] = c > 0.f ? c : 0.f;
    }
}

// ---------------- host orchestration ----------------
static void g3(int tbk, const float* A, const float* B, float* C,
               int M, int N, int K,
               long sA, long sB, long sC, int batch,
               const float* bias, const float* resid, long sR,
               int ldc, int relu)
{
    dim3 grid(N / 128, M / 128, batch);
    if (tbk)
        gemmt_k<1><<<grid, 256, GDSMEM>>>(A, B, C, M, N, K, sA, sB, sC, bias, resid, sR, ldc, relu);
    else
        gemmt_k<0><<<grid, 256, GDSMEM>>>(A, B, C, M, N, K, sA, sB, sC, bias, resid, sR, ldc, relu);
}

extern "C" void kernel_launch(void* const* d_in, const int* in_sizes, int n_in,
                              void* d_out, int out_size)
{
    const float* act   = (const float*)d_in[0];
    const float* comp  = (const float*)d_in[1];
    const float* iou   = (const float*)d_in[2];
    const float* dis   = (const float*)d_in[3];
    const int*   props = (const int*)d_in[4];
    const float* a_w1  = (const float*)d_in[5];
    const float* a_b1  = (const float*)d_in[6];
    const float* a_w2  = (const float*)d_in[7];
    const float* a_b2  = (const float*)d_in[8];
    const float* c_w1  = (const float*)d_in[9];
    const float* c_b1  = (const float*)d_in[10];
    const float* c_w2  = (const float*)d_in[11];
    const float* c_b2  = (const float*)d_in[12];
    const float* fa_w  = (const float*)d_in[13];
    const float* fa_b  = (const float*)d_in[14];
    const float* fc_w  = (const float*)d_in[15];
    const float* fc_b  = (const float*)d_in[16];
    const float* fr_w  = (const float*)d_in[17];
    const float* fr_b  = (const float*)d_in[18];
    float* out = (float*)d_out;

    // idempotent, not a stream op (safe under graph capture); no static guard
    cudaFuncSetAttribute(gemmt_k<0>, cudaFuncAttributeMaxDynamicSharedMemorySize, GDSMEM);
    cudaFuncSetAttribute(gemmt_k<1>, cudaFuncAttributeMaxDynamicSharedMemorySize, GDSMEM);

    float *acos_, *ccos_, *aadj, *cadj, *t1, *t2, *t3, *of, *na, *nc;
    cudaGetSymbolAddress((void**)&acos_, g_act_cos);
    cudaGetSymbolAddress((void**)&ccos_, g_comp_cos);
    cudaGetSymbolAddress((void**)&aadj,  g_act_adj);
    cudaGetSymbolAddress((void**)&cadj,  g_comp_adj);
    cudaGetSymbolAddress((void**)&t1,    g_t1);
    cudaGetSymbolAddress((void**)&t2,    g_t2);
    cudaGetSymbolAddress((void**)&t3,    g_t3);
    cudaGetSymbolAddress((void**)&of,    g_of);
    cudaGetSymbolAddress((void**)&na,    g_norm_a);
    cudaGetSymbolAddress((void**)&nc,    g_norm_c);

    // 1) Gram matrices (A @ A^T per batch)
    g3(1, act, act, acos_, PP, PP, DDA,
       (long)PP * DDA, (long)PP * DDA, (long)PP * PP, BQ, 0, 0, 0, PP, 0);
    g3(1, comp, comp, ccos_, PP, PP, DDC,
       (long)PP * DDC, (long)PP * DDC, (long)PP * PP, BQ, 0, 0, 0, PP, 0);

    // 2) cosine normalization
    norms_k<<<(BQ * PP + 255) / 256, 256>>>(acos_, na);
    norms_k<<<(BQ * PP + 255) / 256, 256>>>(ccos_, nc);
    cosnorm_k<<<4096, 256>>>(acos_, na);
    cosnorm_k<<<4096, 256>>>(ccos_, nc);

    // 3) graph construction
    build_adj_k<<<(BQ * PP) / 4, 128>>>(iou, dis, acos_, ccos_, props, aadj, cadj);

    // 4) Act GCN
    g3(0, act, a_w1, t1, BQ * PP, HID, DDA, 0, 0, 0, 1, 0, 0, 0, HID, 0);
    g3(0, aadj, t1, t2, PP, HID, PP,
       (long)PP * PP, (long)PP * HID, (long)PP * HID, BQ, a_b1, 0, 0, HID, 1);
    g3(0, t2, a_w2, t3, BQ * PP, DDA, HID, 0, 0, 0, 1, 0, 0, 0, DDA, 0);
    g3(0, aadj, t3, of, PP, DDA, PP,
       (long)PP * PP, (long)PP * DDA, (long)PP * DDA, BQ, a_b2, act, (long)PP * DDA, DDA, 0);
    // head 1 (act) must run before comp chain overwrites `of`
    {
        dim3 grid((21 + BN - 1) / BN, (BQ * PP + BM - 1) / BM, 1);
        sgemm_k<<<grid, 256>>>(of, fa_w, out, BQ * PP, 21, DDA, fa_b, 81);
    }

    // 5) Comp GCN
    g3(0, comp, c_w1, t1, BQ * PP, HID, DDC, 0, 0, 0, 1, 0, 0, 0, HID, 0);
    g3(0, cadj, t1, t2, PP, HID, PP,
       (long)PP * PP, (long)PP * HID, (long)PP * HID, BQ, c_b1, 0, 0, HID, 1);
    g3(0, t2, c_w2, t3, BQ * PP, DDC, HID, 0, 0, 0, 1, 0, 0, 0, DDC, 0);
    g3(0, cadj, t3, of, PP, DDC, PP,
       (long)PP * PP, (long)PP * DDC, (long)PP * DDC, BQ, c_b2, comp, (long)PP * DDC, DDC, 0);
    {
        dim3 grid((20 + BN - 1) / BN, (BQ * PP + BM - 1) / BM, 1);
        sgemm_k<<<grid, 256>>>(of, fc_w, out + 21, BQ * PP, 20, DDC, fc_b, 81);
    }
    {
        dim3 grid((40 + BN - 1) / BN, (BQ * PP + BM - 1) / BM, 1);
        sgemm_k<<<grid, 256>>>(of, fr_w, out + 41, BQ * PP, 40, DDC, fr_b, 81);
    }
}

// round 4
// speedup vs baseline: 3.9914x; 1.3186x over previous
#include <cuda_runtime.h>
#include <cuda_bf16.h>
#include <math.h>
#include <stdint.h>

#define BQ 4
#define PP 1024
#define DDA 1024
#define DDC 3072
#define HID 512
typedef __nv_bfloat16 bf16;

// ---------------- scratch (static device memory, no allocation) ----------------
__device__ float g_acos[(size_t)BQ*PP*PP];
__device__ float g_ccos[(size_t)BQ*PP*PP];
__device__ float g_na[BQ*PP];
__device__ float g_nc[BQ*PP];
__device__ bf16 g_ah[(size_t)BQ*PP*DDA], g_al[(size_t)BQ*PP*DDA];
__device__ bf16 g_ch[(size_t)BQ*PP*DDC], g_cl[(size_t)BQ*PP*DDC];
__device__ bf16 g_aadjh[(size_t)BQ*PP*PP], g_aadjl[(size_t)BQ*PP*PP];
__device__ bf16 g_cadjh[(size_t)BQ*PP*PP], g_cadjl[(size_t)BQ*PP*PP];
__device__ bf16 g_w1ah[DDA*HID], g_w1al[DDA*HID];
__device__ bf16 g_w2ah[HID*DDA], g_w2al[HID*DDA];
__device__ bf16 g_w1ch[DDC*HID], g_w1cl[DDC*HID];
__device__ bf16 g_w2ch[HID*DDC], g_w2cl[HID*DDC];
__device__ bf16 g_t1h[(size_t)BQ*PP*HID], g_t1l[(size_t)BQ*PP*HID];
__device__ bf16 g_t2h[(size_t)BQ*PP*HID], g_t2l[(size_t)BQ*PP*HID];
__device__ bf16 g_t3h[(size_t)BQ*PP*DDC], g_t3l[(size_t)BQ*PP*DDC];
__device__ bf16 g_ofah[(size_t)BQ*PP*DDA], g_ofal[(size_t)BQ*PP*DDA];
__device__ bf16 g_ofch[(size_t)BQ*PP*DDC], g_ofcl[(size_t)BQ*PP*DDC];
__device__ bf16 g_wp1h[DDA*128], g_wp1l[DDA*128];
__device__ bf16 g_wp2h[DDC*128], g_wp2l[DDC*128];
__device__ float g_bp1[128], g_bp2[128];

// ====================== low-level helpers ======================
__device__ __forceinline__ uint32_t smem_u32(const void* p) {
    uint32_t a;
    asm("{ .reg .u64 t; cvta.to.shared.u64 t, %1; cvt.u32.u64 %0, t; }" : "=r"(a) : "l"(p));
    return a;
}
__device__ __forceinline__ uint32_t pack_bf16x2(float lo_e, float hi_e) {
    // low16 = bf16rn(lo_e), high16 = bf16rn(hi_e)
    uint32_t r;
    asm("cvt.rn.bf16x2.f32 %0, %1, %2;" : "=r"(r) : "f"(hi_e), "f"(lo_e));
    return r;
}
__device__ __forceinline__ void split2(float x, float y, uint32_t& h, uint32_t& l) {
    uint32_t ux = __float_as_uint(x), uy = __float_as_uint(y);
    h = __byte_perm(ux, uy, 0x7632);
    float lx = x - __uint_as_float(ux & 0xFFFF0000u);
    float ly = y - __uint_as_float(uy & 0xFFFF0000u);
    l = pack_bf16x2(lx, ly);
}
__device__ __forceinline__ void ldmx4(uint32_t* r, uint32_t addr) {
    asm volatile("ldmatrix.sync.aligned.m8n8.x4.shared.b16 {%0,%1,%2,%3}, [%4];"
                 : "=r"(r[0]), "=r"(r[1]), "=r"(r[2]), "=r"(r[3]) : "r"(addr));
}
__device__ __forceinline__ void ldmx2(uint32_t* r, uint32_t addr) {
    asm volatile("ldmatrix.sync.aligned.m8n8.x2.shared.b16 {%0,%1}, [%2];"
                 : "=r"(r[0]), "=r"(r[1]) : "r"(addr));
}
__device__ __forceinline__ void ldmx2t(uint32_t* r, uint32_t addr) {
    asm volatile("ldmatrix.sync.aligned.m8n8.x2.trans.shared.b16 {%0,%1}, [%2];"
                 : "=r"(r[0]), "=r"(r[1]) : "r"(addr));
}
__device__ __forceinline__ void mma_bf16(float* c, const uint32_t* a, const uint32_t* b) {
    asm volatile(
        "mma.sync.aligned.m16n8k16.row.col.f32.bf16.bf16.f32 "
        "{%0,%1,%2,%3}, {%4,%5,%6,%7}, {%8,%9}, {%0,%1,%2,%3};"
        : "+f"(c[0]), "+f"(c[1]), "+f"(c[2]), "+f"(c[3])
        : "r"(a[0]), "r"(a[1]), "r"(a[2]), "r"(a[3]), "r"(b[0]), "r"(b[1]));
}
__device__ __forceinline__ void cp16(uint32_t dst, const void* src) {
    asm volatile("cp.async.cg.shared.global [%0], [%1], 16;" :: "r"(dst), "l"(src) : "memory");
}
#define CP_COMMIT() asm volatile("cp.async.commit_group;" ::: "memory")
#define CP_WAIT1()  asm volatile("cp.async.wait_group 1;" ::: "memory")

// ====================== bf16x3 multistage mma GEMM ======================
// C = A @ B (+bias, +resid, relu). A: hi/lo [M,K] bf16 row-major.
// TBK=1: B hi/lo [N,K] (K-major rows, like A). TBK=0: B hi/lo [K,N].
// Output: fp32 C and/or split bf16 Ch/Cl. ncap>0 => "head mode": grid.x==1,
// guarded scalar fp32 stores to ldc (may be odd).
// M%128==0, K%32==0; vector mode needs N%128==0.
#define AROWB 80
#define ATILE 10240          // 128*80 per (hi|lo)
#define ASTG  20480          // A stage bytes
#define BSTG1 20480          // B stage bytes, TBK=1
#define BSTG0 16384          // B stage bytes, TBK=0 (2 * 32*256)

template<int TBK>
__global__ __launch_bounds__(256, 1)
void gemmx_k(const bf16* __restrict__ Ah, const bf16* __restrict__ Al,
             const bf16* __restrict__ Bh, const bf16* __restrict__ Bl,
             float* __restrict__ C, bf16* __restrict__ Ch, bf16* __restrict__ Cl,
             int N, int K, long sA, long sB, long sC,
             const float* __restrict__ bias,
             const float* __restrict__ resid, long sR,
             int ldc, int relu_flag, int ncap)
{
    constexpr int BSTG = TBK ? BSTG1 : BSTG0;
    constexpr int SB = ASTG + BSTG;
    extern __shared__ char sm[];
    uint32_t smb = smem_u32(sm);

    const int tid = threadIdx.x;
    const int lane = tid & 31;
    const int wid = tid >> 5;
    const int wm = (wid >> 2) * 64;
    const int wn = (wid & 3) * 32;

    long bz = blockIdx.z;
    const int bm = blockIdx.y * 128;
    const int bn = blockIdx.x * 128;
    const bf16* Ahb = Ah + bz * sA + (size_t)bm * K;
    const bf16* Alb = Al + bz * sA + (size_t)bm * K;
    const bf16* Bhb = TBK ? (Bh + bz * sB + (size_t)bn * K) : (Bh + bz * sB + bn);
    const bf16* Blb = TBK ? (Bl + bz * sB + (size_t)bn * K) : (Bl + bz * sB + bn);
    float* Cb = C ? C + bz * sC : (float*)0;
    bf16* Chb = Ch ? Ch + bz * sC : (bf16*)0;
    bf16* Clb = Cl ? Cl + bz * sC : (bf16*)0;
    const float* Rb = resid ? resid + bz * sR : (const float*)0;

    float acc[4][4][4];
#pragma unroll
    for (int i = 0; i < 4; i++)
#pragma unroll
        for (int j = 0; j < 4; j++)
#pragma unroll
            for (int r = 0; r < 4; r++) acc[i][j][r] = 0.f;

    const int nch = K >> 5;

    // ---- async stage loader ----
    auto load_stage = [&](int kt, int s) {
        uint32_t base = smb + (uint32_t)s * SB;
        int k0 = kt << 5;
#pragma unroll
        for (int it = 0; it < 4; it++) {
            int id = it * 256 + tid;
            int hl = id >> 9, rid = id & 511;
            int row = rid >> 2, c = rid & 3;
            const bf16* src = (hl ? Alb : Ahb) + (size_t)row * K + k0 + c * 8;
            cp16(base + hl * ATILE + row * AROWB + c * 16, src);
        }
        if (TBK) {
#pragma unroll
            for (int it = 0; it < 4; it++) {
                int id = it * 256 + tid;
                int hl = id >> 9, rid = id & 511;
                int row = rid >> 2, c = rid & 3;
                const bf16* src = (hl ? Blb : Bhb) + (size_t)row * K + k0 + c * 8;
                cp16(base + ASTG + hl * ATILE + row * AROWB + c * 16, src);
            }
        } else {
#pragma unroll
            for (int it = 0; it < 4; it++) {
                int id = it * 256 + tid;
                int hl = id >> 9, rid = id & 511;
                int k = rid >> 4, c = rid & 15;
                const bf16* src = (hl ? Blb : Bhb) + (size_t)(k0 + k) * N + c * 8;
                cp16(base + ASTG + hl * 8192 + k * 256 + ((c ^ (k & 7)) << 4), src);
            }
        }
        CP_COMMIT();
    };

    load_stage(0, 0);
    load_stage(1, 1);

    for (int kt = 0; kt < nch; kt++) {
        CP_WAIT1();
        __syncthreads();
        int s = kt - (kt / 3) * 3;
        uint32_t aB = smb + (uint32_t)s * SB;
        uint32_t bB = aB + ASTG;

#pragma unroll
        for (int kh = 0; kh < 2; kh++) {
            uint32_t ahi[4][4], alo[4][4], bhi[4][2], blo[4][2];
            {
                int arow = wm + (lane & 15);
                uint32_t aoff = (uint32_t)(kh * 32 + ((lane >> 4) << 4));
#pragma unroll
                for (int i = 0; i < 4; i++) {
                    uint32_t ro = (uint32_t)(arow + i * 16) * AROWB + aoff;
                    ldmx4(ahi[i], aB + ro);
                    ldmx4(alo[i], aB + ATILE + ro);
                }
            }
            if (TBK) {
                int brow = wn + (lane & 7);
                uint32_t boff = (uint32_t)(kh * 32 + (((lane >> 3) & 1) << 4));
#pragma unroll
                for (int j = 0; j < 4; j++) {
                    uint32_t ro = (uint32_t)(brow + j * 8) * AROWB + boff;
                    ldmx2(bhi[j], bB + ro);
                    ldmx2(blo[j], bB + ATILE + ro);
                }
            } else {
                int kl = kh * 16 + (lane & 7) + ((lane >> 3) & 1) * 8;
                uint32_t kro = (uint32_t)kl << 8;
                int cbase = wn >> 3;
#pragma unroll
                for (int j = 0; j < 4; j++) {
                    uint32_t c2 = (uint32_t)((cbase + j) ^ (kl & 7)) << 4;
                    ldmx2t(bhi[j], bB + kro + c2);
                    ldmx2t(blo[j], bB + 8192 + kro + c2);
                }
            }
#pragma unroll
            for (int i = 0; i < 4; i++)
#pragma unroll
                for (int j = 0; j < 4; j++)
                    mma_bf16(acc[i][j], ahi[i], bhi[j]);
#pragma unroll
            for (int i = 0; i < 4; i++)
#pragma unroll
                for (int j = 0; j < 4; j++)
                    mma_bf16(acc[i][j], ahi[i], blo[j]);
#pragma unroll
            for (int i = 0; i < 4; i++)
#pragma unroll
                for (int j = 0; j < 4; j++)
                    mma_bf16(acc[i][j], alo[i], bhi[j]);
        }

        if (kt + 2 < nch) {
            int s2 = kt + 2;
            s2 = s2 - (s2 / 3) * 3;
            load_stage(kt + 2, s2);
        } else {
            CP_COMMIT();   // keep group counting uniform for wait_group 1
        }
    }

    // ---- epilogue ----
#pragma unroll
    for (int i = 0; i < 4; i++) {
        int r0 = bm + wm + i * 16 + (lane >> 2);
        int r1 = r0 + 8;
#pragma unroll
        for (int j = 0; j < 4; j++) {
            int gc = bn + wn + j * 8 + (lane & 3) * 2;
            float2 v0 = make_float2(acc[i][j][0], acc[i][j][1]);
            float2 v1 = make_float2(acc[i][j][2], acc[i][j][3]);
            if (bias) {
                float2 bv = *reinterpret_cast<const float2*>(bias + gc);
                v0.x += bv.x; v0.y += bv.y;
                v1.x += bv.x; v1.y += bv.y;
            }
            if (Rb) {
                float2 q0 = *reinterpret_cast<const float2*>(Rb + (size_t)r0 * ldc + gc);
                float2 q1 = *reinterpret_cast<const float2*>(Rb + (size_t)r1 * ldc + gc);
                v0.x += q0.x; v0.y += q0.y;
                v1.x += q1.x; v1.y += q1.y;
            }
            if (relu_flag) {
                v0.x = fmaxf(v0.x, 0.f); v0.y = fmaxf(v0.y, 0.f);
                v1.x = fmaxf(v1.x, 0.f); v1.y = fmaxf(v1.y, 0.f);
            }
            if (Cb) {
                if (ncap == 0) {
                    *reinterpret_cast<float2*>(Cb + (size_t)r0 * ldc + gc) = v0;
                    *reinterpret_cast<float2*>(Cb + (size_t)r1 * ldc + gc) = v1;
                } else {
                    if (gc < ncap)     { Cb[(size_t)r0 * ldc + gc] = v0.x;     Cb[(size_t)r1 * ldc + gc] = v1.x; }
                    if (gc + 1 < ncap) { Cb[(size_t)r0 * ldc + gc + 1] = v0.y; Cb[(size_t)r1 * ldc + gc + 1] = v1.y; }
                }
            }
            if (Chb) {
                uint32_t h0, l0, h1, l1;
                split2(v0.x, v0.y, h0, l0);
                split2(v1.x, v1.y, h1, l1);
                *reinterpret_cast<uint32_t*>(Chb + (size_t)r0 * ldc + gc) = h0;
                *reinterpret_cast<uint32_t*>(Clb + (size_t)r0 * ldc + gc) = l0;
                *reinterpret_cast<uint32_t*>(Chb + (size_t)r1 * ldc + gc) = h1;
                *reinterpret_cast<uint32_t*>(Clb + (size_t)r1 * ldc + gc) = l1;
            }
        }
    }
}

// ====================== elementwise kernels ======================
__global__ void split_k(const float* __restrict__ s, bf16* __restrict__ h,
                        bf16* __restrict__ l, size_t n4)
{
    for (size_t i = (size_t)blockIdx.x * blockDim.x + threadIdx.x; i < n4;
         i += (size_t)gridDim.x * blockDim.x) {
        float4 v = reinterpret_cast<const float4*>(s)[i];
        uint32_t h0, l0, h1, l1;
        split2(v.x, v.y, h0, l0);
        split2(v.z, v.w, h1, l1);
        reinterpret_cast<uint2*>(h)[i] = make_uint2(h0, h1);
        reinterpret_cast<uint2*>(l)[i] = make_uint2(l0, l1);
    }
}

__global__ void zero_k(uint4* __restrict__ p, size_t n16)
{
    for (size_t i = (size_t)blockIdx.x * blockDim.x + threadIdx.x; i < n16;
         i += (size_t)gridDim.x * blockDim.x)
        p[i] = make_uint4(0, 0, 0, 0);
}

__global__ void padsplit_k(const float* __restrict__ src, bf16* __restrict__ h,
                           bf16* __restrict__ l, int K, int Nsrc, int col0)
{
    int total = K * Nsrc;
    for (int i = blockIdx.x * blockDim.x + threadIdx.x; i < total;
         i += gridDim.x * blockDim.x) {
        int k = i / Nsrc, n = i - k * Nsrc;
        float v = src[i];
        uint32_t u = __float_as_uint(v);
        float lv = v - __uint_as_float(u & 0xFFFF0000u);
        size_t d = (size_t)k * 128 + col0 + n;
        reinterpret_cast<unsigned short*>(h)[d] = (unsigned short)(u >> 16);
        reinterpret_cast<unsigned short*>(l)[d] = (unsigned short)(pack_bf16x2(lv, lv) & 0xFFFFu);
    }
}

__global__ void copyf_k(float* __restrict__ dst, const float* __restrict__ src, int n)
{
    int i = blockIdx.x * blockDim.x + threadIdx.x;
    if (i < n) dst[i] = src[i];
}

__global__ void norms_k(const float* __restrict__ G, float* __restrict__ nrm)
{
    int i = blockIdx.x * blockDim.x + threadIdx.x;
    if (i < BQ * PP) {
        int b = i >> 10, p = i & (PP - 1);
        nrm[i] = sqrtf(G[((size_t)b * PP + p) * PP + p]);
    }
}

__global__ void cosnorm_k(float* __restrict__ G, const float* __restrict__ nrm)
{
    size_t total = (size_t)BQ * PP * PP;
    for (size_t idx = (size_t)blockIdx.x * blockDim.x + threadIdx.x; idx < total;
         idx += (size_t)gridDim.x * blockDim.x) {
        int q = (int)(idx & (PP - 1));
        size_t r = idx >> 10;
        int b = (int)(r >> 10);
        float np = nrm[r];
        float nq = nrm[((size_t)b << 10) + q];
        G[idx] = G[idx] / (np * nq + 1e-6f);
    }
}

// ---------------- graph construction (one warp per row) ----------------
__device__ __forceinline__ void warp_argmin(float& v, int& l)
{
#pragma unroll
    for (int off = 16; off; off >>= 1) {
        float ov = __shfl_down_sync(0xffffffffu, v, off);
        int ol = __shfl_down_sync(0xffffffffu, l, off);
        if (ov < v) { v = ov; l = ol; }
    }
    v = __shfl_sync(0xffffffffu, v, 0);
    l = __shfl_sync(0xffffffffu, l, 0);
}
__device__ __forceinline__ void warp_argmax(float& v, int& l)
{
#pragma unroll
    for (int off = 16; off; off >>= 1) {
        float ov = __shfl_down_sync(0xffffffffu, v, off);
        int ol = __shfl_down_sync(0xffffffffu, l, off);
        if (ov > v) { v = ov; l = ol; }
    }
    v = __shfl_sync(0xffffffffu, v, 0);
    l = __shfl_sync(0xffffffffu, l, 0);
}

__global__ __launch_bounds__(128)
void build_adj_k(const float* __restrict__ iou, const float* __restrict__ dis,
                 const float* __restrict__ acos_, const float* __restrict__ ccos_,
                 const int* __restrict__ props,
                 bf16* __restrict__ awh, bf16* __restrict__ awl,
                 bf16* __restrict__ cwh, bf16* __restrict__ cwl)
{
    int warp = threadIdx.x >> 5, lane = threadIdx.x & 31;
    int row = blockIdx.x * (blockDim.x >> 5) + warp;
    if (row >= BQ * PP) return;
    int b = row >> 10;
    int p = row & (PP - 1);
    const float* iour = iou + (size_t)row * PP;
    const float* disr = dis + (size_t)row * PP;
    const float* ar = acos_ + (size_t)row * PP;
    const float* cr = ccos_ + (size_t)row * PP;
    int pn = props[b];
    bool pv = p < pn;

    float dv[6]; int di[6];
#pragma unroll
    for (int j = 0; j < 6; j++) { dv[j] = 3.0e38f; di[j] = -1; }
    float sv[2] = {-3.0e38f, -3.0e38f};
    int si[2] = {-1, -1};

    for (int q = lane; q < PP; q += 32) {
        float io = iour[q];
        bool ip = io > 0.0f;
        bool qv = q < pn;
        bool v2 = pv && qv;

        float dm = v2 ? (ip ? 2.0f : disr[q]) : 1.0e9f;
        if (dm < dv[5]) {
            dv[5] = dm; di[5] = q;
#pragma unroll
            for (int j = 5; j > 0; j--) {
                if (dv[j] < dv[j - 1]) {
                    float tv = dv[j]; dv[j] = dv[j - 1]; dv[j - 1] = tv;
                    int ti = di[j]; di[j] = di[j - 1]; di[j - 1] = ti;
                }
            }
        }
        float sm = v2 ? (ip ? 0.0f : (ar[q] - (q == p ? 1.0f : 0.0f))) : -1.0e9f;
        if (sm > sv[1]) {
            if (sm > sv[0]) { sv[1] = sv[0]; si[1] = si[0]; sv[0] = sm; si[0] = q; }
            else            { sv[1] = sm; si[1] = q; }
        }
    }

    int sel[8];
    {
        int ptr = 0;
        for (int k = 0; k < 6; k++) {
            float cv = (ptr < 6) ? dv[ptr] : 3.0e38f;
            int ci = (ptr < 6) ? di[ptr] : -1;
            float v = cv; int l = lane;
            warp_argmin(v, l);
            sel[k] = __shfl_sync(0xffffffffu, ci, l);
            if (lane == l) ptr++;
        }
    }
    {
        int ptr = 0;
        for (int k = 0; k < 2; k++) {
            float cv = (ptr < 2) ? sv[ptr] : -3.0e38f;
            int ci = (ptr < 2) ? si[ptr] : -1;
            float v = cv; int l = lane;
            warp_argmax(v, l);
            sel[6 + k] = __shfl_sync(0xffffffffu, ci, l);
            if (lane == l) ptr++;
        }
    }
#pragma unroll
    for (int k = 0; k < 8; k++) {
        int q = sel[k];
        bool ok = (q >= 0) && pv && (q < pn) && !(iour[q] > 0.0f);
        sel[k] = ok ? q : -1;
    }

    unsigned mbits = 0;
    for (int i = 0; i < 32; i++) {
        int q = lane + 32 * i;
        float io = iour[q];
        bool bit = (q != p) && (io > 0.7f);
#pragma unroll
        for (int k = 0; k < 8; k++) bit |= (sel[k] == q);
        mbits |= (bit ? 1u : 0u) << i;
    }
    int cnt = __popc(mbits);
#pragma unroll
    for (int off = 16; off; off >>= 1) cnt += __shfl_xor_sync(0xffffffffu, cnt, off);
    float inv = 1.0f / ((float)cnt + 1e-6f);

    unsigned short* ah_ = reinterpret_cast<unsigned short*>(awh) + (size_t)row * PP;
    unsigned short* al_ = reinterpret_cast<unsigned short*>(awl) + (size_t)row * PP;
    unsigned short* ch_ = reinterpret_cast<unsigned short*>(cwh) + (size_t)row * PP;
    unsigned short* cl_ = reinterpret_cast<unsigned short*>(cwl) + (size_t)row * PP;
    for (int i = 0; i < 32; i++) {
        int q = lane + 32 * i;
        float m = ((mbits >> i) & 1u) ? inv : 0.0f;
        if (q == p) m += 1.0f;
        float a = fmaxf(ar[q] * m, 0.f);
        float c = fmaxf(cr[q] * m, 0.f);
        uint32_t ua = __float_as_uint(a);
        uint32_t uc = __float_as_uint(c);
        float la = a - __uint_as_float(ua & 0xFFFF0000u);
        float lc = c - __uint_as_float(uc & 0xFFFF0000u);
        ah_[q] = (unsigned short)(ua >> 16);
        al_[q] = (unsigned short)(pack_bf16x2(la, la) & 0xFFFFu);
        ch_[q] = (unsigned short)(uc >> 16);
        cl_[q] = (unsigned short)(pack_bf16x2(lc, lc) & 0xFFFFu);
    }
}

// ---------------- host orchestration ----------------
static void gx(int tbk, const bf16* Ah, const bf16* Al, const bf16* Bh, const bf16* Bl,
               float* C, bf16* Ch, bf16* Cl,
               int M, int N, int K, long sA, long sB, long sC, int batch,
               const float* bias, const float* resid, long sR,
               int ldc, int relu, int ncap)
{
    int smem = 3 * (ASTG + (tbk ? BSTG1 : BSTG0));
    int gx_ = ncap ? 1 : N / 128;
    dim3 grid(gx_, M / 128, batch);
    if (tbk) {
        cudaFuncSetAttribute(gemmx_k<1>, cudaFuncAttributeMaxDynamicSharedMemorySize, smem);
        gemmx_k<1><<<grid, 256, smem>>>(Ah, Al, Bh, Bl, C, Ch, Cl, N, K, sA, sB, sC,
                                        bias, resid, sR, ldc, relu, ncap);
    } else {
        cudaFuncSetAttribute(gemmx_k<0>, cudaFuncAttributeMaxDynamicSharedMemorySize, smem);
        gemmx_k<0><<<grid, 256, smem>>>(Ah, Al, Bh, Bl, C, Ch, Cl, N, K, sA, sB, sC,
                                        bias, resid, sR, ldc, relu, ncap);
    }
}

#define SYM(var, sym) cudaGetSymbolAddress((void**)&var, sym)

extern "C" void kernel_launch(void* const* d_in, const int* in_sizes, int n_in,
                              void* d_out, int out_size)
{
    const float* act   = (const float*)d_in[0];
    const float* comp  = (const float*)d_in[1];
    const float* iou   = (const float*)d_in[2];
    const float* dis   = (const float*)d_in[3];
    const int*   props = (const int*)d_in[4];
    const float* a_w1  = (const float*)d_in[5];
    const float* a_b1  = (const float*)d_in[6];
    const float* a_w2  = (const float*)d_in[7];
    const float* a_b2  = (const float*)d_in[8];
    const float* c_w1  = (const float*)d_in[9];
    const float* c_b1  = (const float*)d_in[10];
    const float* c_w2  = (const float*)d_in[11];
    const float* c_b2  = (const float*)d_in[12];
    const float* fa_w  = (const float*)d_in[13];
    const float* fa_b  = (const float*)d_in[14];
    const float* fc_w  = (const float*)d_in[15];
    const float* fc_b  = (const float*)d_in[16];
    const float* fr_w  = (const float*)d_in[17];
    const float* fr_b  = (const float*)d_in[18];
    float* out = (float*)d_out;

    float *acos_, *ccos_, *na, *nc, *bp1, *bp2;
    bf16 *ah, *al, *ch_, *cl_, *aadjh, *aadjl, *cadjh, *cadjl;
    bf16 *w1ah, *w1al, *w2ah, *w2al, *w1ch, *w1cl, *w2ch, *w2cl;
    bf16 *t1h, *t1l, *t2h, *t2l, *t3h, *t3l, *ofah, *ofal, *ofch, *ofcl;
    bf16 *wp1h, *wp1l, *wp2h, *wp2l;
    SYM(acos_, g_acos); SYM(ccos_, g_ccos); SYM(na, g_na); SYM(nc, g_nc);
    SYM(ah, g_ah); SYM(al, g_al); SYM(ch_, g_ch); SYM(cl_, g_cl);
    SYM(aadjh, g_aadjh); SYM(aadjl, g_aadjl); SYM(cadjh, g_cadjh); SYM(cadjl, g_cadjl);
    SYM(w1ah, g_w1ah); SYM(w1al, g_w1al); SYM(w2ah, g_w2ah); SYM(w2al, g_w2al);
    SYM(w1ch, g_w1ch); SYM(w1cl, g_w1cl); SYM(w2ch, g_w2ch); SYM(w2cl, g_w2cl);
    SYM(t1h, g_t1h); SYM(t1l, g_t1l); SYM(t2h, g_t2h); SYM(t2l, g_t2l);
    SYM(t3h, g_t3h); SYM(t3l, g_t3l);
    SYM(ofah, g_ofah); SYM(ofal, g_ofal); SYM(ofch, g_ofch); SYM(ofcl, g_ofcl);
    SYM(wp1h, g_wp1h); SYM(wp1l, g_wp1l); SYM(wp2h, g_wp2h); SYM(wp2l, g_wp2l);
    SYM(bp1, g_bp1); SYM(bp2, g_bp2);

    // 0) split inputs + weights to bf16 hi/lo
    split_k<<<1024, 256>>>(act, ah, al, (size_t)BQ * PP * DDA / 4);
    split_k<<<2048, 256>>>(comp, ch_, cl_, (size_t)BQ * PP * DDC / 4);
    split_k<<<256, 256>>>(a_w1, w1ah, w1al, (size_t)DDA * HID / 4);
    split_k<<<256, 256>>>(a_w2, w2ah, w2al, (size_t)HID * DDA / 4);
    split_k<<<512, 256>>>(c_w1, w1ch, w1cl, (size_t)DDC * HID / 4);
    split_k<<<512, 256>>>(c_w2, w2ch, w2cl, (size_t)HID * DDC / 4);

    // head weight pads (zero-fill, then scatter + split)
    zero_k<<<64, 256>>>((uint4*)wp1h, (size_t)DDA * 128 * 2 / 16);
    zero_k<<<64, 256>>>((uint4*)wp1l, (size_t)DDA * 128 * 2 / 16);
    zero_k<<<128, 256>>>((uint4*)wp2h, (size_t)DDC * 128 * 2 / 16);
    zero_k<<<128, 256>>>((uint4*)wp2l, (size_t)DDC * 128 * 2 / 16);
    zero_k<<<1, 64>>>((uint4*)bp1, 128 * 4 / 16);
    zero_k<<<1, 64>>>((uint4*)bp2, 128 * 4 / 16);
    padsplit_k<<<128, 256>>>(fa_w, wp1h, wp1l, DDA, 21, 0);
    padsplit_k<<<256, 256>>>(fc_w, wp2h, wp2l, DDC, 20, 0);
    padsplit_k<<<512, 256>>>(fr_w, wp2h, wp2l, DDC, 40, 20);
    copyf_k<<<1, 32>>>(bp1, fa_b, 21);
    copyf_k<<<1, 32>>>(bp2, fc_b, 20);
    copyf_k<<<1, 64>>>(bp2 + 20, fr_b, 40);

    // 1) Gram matrices (A @ A^T) -> fp32 cos buffers
    gx(1, ah, al, ah, al, acos_, 0, 0, PP, PP, DDA,
       (long)PP * DDA, (long)PP * DDA, (long)PP * PP, BQ, 0, 0, 0, PP, 0, 0);
    gx(1, ch_, cl_, ch_, cl_, ccos_, 0, 0, PP, PP, DDC,
       (long)PP * DDC, (long)PP * DDC, (long)PP * PP, BQ, 0, 0, 0, PP, 0, 0);

    // 2) cosine normalization
    norms_k<<<(BQ * PP + 255) / 256, 256>>>(acos_, na);
    norms_k<<<(BQ * PP + 255) / 256, 256>>>(ccos_, nc);
    cosnorm_k<<<4096, 256>>>(acos_, na);
    cosnorm_k<<<4096, 256>>>(ccos_, nc);

    // 3) graph construction -> split adjacency
    build_adj_k<<<(BQ * PP) / 4, 128>>>(iou, dis, acos_, ccos_, props,
                                        aadjh, aadjl, cadjh, cadjl);

    // 4) Act GCN chain (all bf16x3 mma)
    gx(0, ah, al, w1ah, w1al, 0, t1h, t1l, BQ * PP, HID, DDA,
       0, 0, 0, 1, 0, 0, 0, HID, 0, 0);
    gx(0, aadjh, aadjl, t1h, t1l, 0, t2h, t2l, PP, HID, PP,
       (long)PP * PP, (long)PP * HID, (long)PP * HID, BQ, a_b1, 0, 0, HID, 1, 0);
    gx(0, t2h, t2l, w2ah, w2al, 0, t3h, t3l, BQ * PP, DDA, HID,
       0, 0, 0, 1, 0, 0, 0, DDA, 0, 0);
    gx(0, aadjh, aadjl, t3h, t3l, 0, ofah, ofal, PP, DDA, PP,
       (long)PP * PP, (long)PP * DDA, (long)PP * DDA, BQ,
       a_b2, act, (long)PP * DDA, DDA, 0, 0);
    // act head: out[:, 0:21]
    gx(0, ofah, ofal, wp1h, wp1l, out, 0, 0, BQ * PP, 128, DDA,
       0, 0, 0, 1, bp1, 0, 0, 81, 0, 21);

    // 5) Comp GCN chain
    gx(0, ch_, cl_, w1ch, w1cl, 0, t1h, t1l, BQ * PP, HID, DDC,
       0, 0, 0, 1, 0, 0, 0, HID, 0, 0);
    gx(0, cadjh, cadjl, t1h, t1l, 0, t2h, t2l, PP, HID, PP,
       (long)PP * PP, (long)PP * HID, (long)PP * HID, BQ, c_b1, 0, 0, HID, 1, 0);
    gx(0, t2h, t2l, w2ch, w2cl, 0, t3h, t3l, BQ * PP, DDC, HID,
       0, 0, 0, 1, 0, 0, 0, DDC, 0, 0);
    gx(0, cadjh, cadjl, t3h, t3l, 0, ofch, ofcl, PP, DDC, PP,
       (long)PP * PP, (long)PP * DDC, (long)PP * DDC, BQ,
       c_b2, comp, (long)PP * DDC, DDC, 0, 0);
    // comp heads: out[:, 21:81] (fc cols 0..19, fr cols 20..59 in padded panel)
    gx(0, ofch, ofcl, wp2h, wp2l, out + 21, 0, 0, BQ * PP, 128, DDC,
       0, 0, 0, 1, bp2, 0, 0, 81, 0, 60);
}

// round 5
// speedup vs baseline: 4.8578x; 1.2171x over previous
#include <cuda_runtime.h>
#include <cuda_bf16.h>
#include <math.h>
#include <stdint.h>

#define BQ 4
#define PP 1024
#define DDA 1024
#define DDC 3072
#define HID 512
typedef __nv_bfloat16 bf16;

// ---------------- scratch (static device memory, no allocation) ----------------
__device__ float g_acos[(size_t)BQ*PP*PP];
__device__ float g_ccos[(size_t)BQ*PP*PP];
__device__ float g_na[BQ*PP];
__device__ float g_nc[BQ*PP];
__device__ bf16 g_ah[(size_t)BQ*PP*DDA], g_al[(size_t)BQ*PP*DDA];
__device__ bf16 g_ch[(size_t)BQ*PP*DDC], g_cl[(size_t)BQ*PP*DDC];
__device__ bf16 g_aadjh[(size_t)BQ*PP*PP], g_aadjl[(size_t)BQ*PP*PP];
__device__ bf16 g_cadjh[(size_t)BQ*PP*PP], g_cadjl[(size_t)BQ*PP*PP];
__device__ bf16 g_w1ah[DDA*HID], g_w1al[DDA*HID];
__device__ bf16 g_w2ah[HID*DDA], g_w2al[HID*DDA];
__device__ bf16 g_w1ch[DDC*HID], g_w1cl[DDC*HID];
__device__ bf16 g_w2ch[HID*DDC], g_w2cl[HID*DDC];
__device__ bf16 g_t1h[(size_t)BQ*PP*HID], g_t1l[(size_t)BQ*PP*HID];
__device__ bf16 g_t2h[(size_t)BQ*PP*HID], g_t2l[(size_t)BQ*PP*HID];
__device__ bf16 g_t3h[(size_t)BQ*PP*DDC], g_t3l[(size_t)BQ*PP*DDC];
__device__ bf16 g_ofah[(size_t)BQ*PP*DDA], g_ofal[(size_t)BQ*PP*DDA];
__device__ bf16 g_ofch[(size_t)BQ*PP*DDC], g_ofcl[(size_t)BQ*PP*DDC];
__device__ bf16 g_wp1h[DDA*128], g_wp1l[DDA*128];
__device__ bf16 g_wp2h[DDC*128], g_wp2l[DDC*128];
__device__ float g_hp1[(size_t)2*BQ*PP*128];
__device__ float g_hp2[(size_t)4*BQ*PP*128];

// ====================== low-level helpers ======================
__device__ __forceinline__ uint32_t smem_u32(const void* p) {
    uint32_t a;
    asm("{ .reg .u64 t; cvta.to.shared.u64 t, %1; cvt.u32.u64 %0, t; }" : "=r"(a) : "l"(p));
    return a;
}
__device__ __forceinline__ uint32_t pack_bf16x2(float lo_e, float hi_e) {
    uint32_t r;
    asm("cvt.rn.bf16x2.f32 %0, %1, %2;" : "=r"(r) : "f"(hi_e), "f"(lo_e));
    return r;
}
__device__ __forceinline__ void split2(float x, float y, uint32_t& h, uint32_t& l) {
    uint32_t ux = __float_as_uint(x), uy = __float_as_uint(y);
    h = __byte_perm(ux, uy, 0x7632);
    float lx = x - __uint_as_float(ux & 0xFFFF0000u);
    float ly = y - __uint_as_float(uy & 0xFFFF0000u);
    l = pack_bf16x2(lx, ly);
}
__device__ __forceinline__ void ldmx4(uint32_t* r, uint32_t addr) {
    asm volatile("ldmatrix.sync.aligned.m8n8.x4.shared.b16 {%0,%1,%2,%3}, [%4];"
                 : "=r"(r[0]), "=r"(r[1]), "=r"(r[2]), "=r"(r[3]) : "r"(addr));
}
__device__ __forceinline__ void ldmx2(uint32_t* r, uint32_t addr) {
    asm volatile("ldmatrix.sync.aligned.m8n8.x2.shared.b16 {%0,%1}, [%2];"
                 : "=r"(r[0]), "=r"(r[1]) : "r"(addr));
}
__device__ __forceinline__ void ldmx2t(uint32_t* r, uint32_t addr) {
    asm volatile("ldmatrix.sync.aligned.m8n8.x2.trans.shared.b16 {%0,%1}, [%2];"
                 : "=r"(r[0]), "=r"(r[1]) : "r"(addr));
}
__device__ __forceinline__ void mma_bf16(float* c, const uint32_t* a, const uint32_t* b) {
    asm volatile(
        "mma.sync.aligned.m16n8k16.row.col.f32.bf16.bf16.f32 "
        "{%0,%1,%2,%3}, {%4,%5,%6,%7}, {%8,%9}, {%0,%1,%2,%3};"
        : "+f"(c[0]), "+f"(c[1]), "+f"(c[2]), "+f"(c[3])
        : "r"(a[0]), "r"(a[1]), "r"(a[2]), "r"(a[3]), "r"(b[0]), "r"(b[1]));
}
__device__ __forceinline__ void cp16(uint32_t dst, const void* src) {
    asm volatile("cp.async.cg.shared.global [%0], [%1], 16;" :: "r"(dst), "l"(src) : "memory");
}
#define CP_COMMIT() asm volatile("cp.async.commit_group;" ::: "memory")
#define CP_WAIT2()  asm volatile("cp.async.wait_group 2;" ::: "memory")

// ====================== bf16x3 multistage mma GEMM ======================
// C = A @ B (+bias, +resid, relu). A: hi/lo [M,K] bf16 row-major.
// TBK=1: B hi/lo [N,K]. TBK=0: B hi/lo [K,N].
// symm: skip blocks bx<by (square symmetric output, mirrored later).
// Klen>0: K-split head mode: blockIdx.x = K-slice, bn=0, partial out at
//         C + blockIdx.x*sC with ldc (no bias/resid/relu).
#define AROWB 80
#define ATILE 10240
#define ASTG  20480
#define BSTG1 20480
#define BSTG0 16384
#define NSTAGE 4

template<int TBK>
__global__ __launch_bounds__(256, 1)
void gemmx_k(const bf16* __restrict__ Ah, const bf16* __restrict__ Al,
             const bf16* __restrict__ Bh, const bf16* __restrict__ Bl,
             float* __restrict__ C, bf16* __restrict__ Ch, bf16* __restrict__ Cl,
             int N, int K, int Klen, int symm,
             long sA, long sB, long sC,
             const float* __restrict__ bias,
             const float* __restrict__ resid, long sR,
             int ldc, int relu_flag)
{
    if (!Klen && symm && blockIdx.x < blockIdx.y) return;
    constexpr int BSTG = TBK ? BSTG1 : BSTG0;
    constexpr int SB = ASTG + BSTG;
    extern __shared__ char sm[];
    uint32_t smb = smem_u32(sm);

    const int tid = threadIdx.x;
    const int lane = tid & 31;
    const int wid = tid >> 5;
    const int wm = (wid >> 2) * 64;
    const int wn = (wid & 3) * 32;

    long bz = blockIdx.z;
    const int bm = blockIdx.y * 128;
    const int bn = Klen ? 0 : blockIdx.x * 128;
    const int kbase = Klen ? blockIdx.x * Klen : 0;
    const int KL = Klen ? Klen : K;

    const bf16* Ahb = Ah + bz * sA + (size_t)bm * K + kbase;
    const bf16* Alb = Al + bz * sA + (size_t)bm * K + kbase;
    const bf16* Bhb = TBK ? (Bh + bz * sB + (size_t)bn * K + kbase)
                          : (Bh + bz * sB + (size_t)kbase * N + bn);
    const bf16* Blb = TBK ? (Bl + bz * sB + (size_t)bn * K + kbase)
                          : (Bl + bz * sB + (size_t)kbase * N + bn);
    float* Cb = C ? (Klen ? C + (size_t)blockIdx.x * sC : C + bz * sC) : (float*)0;
    bf16* Chb = Ch ? Ch + bz * sC : (bf16*)0;
    bf16* Clb = Cl ? Cl + bz * sC : (bf16*)0;
    const float* Rb = resid ? resid + bz * sR : (const float*)0;

    float acc[4][4][4];
#pragma unroll
    for (int i = 0; i < 4; i++)
#pragma unroll
        for (int j = 0; j < 4; j++)
#pragma unroll
            for (int r = 0; r < 4; r++) acc[i][j][r] = 0.f;

    const int nch = KL >> 5;   // always >= 16 in this network

    auto load_stage = [&](int kt, int s) {
        uint32_t base = smb + (uint32_t)s * SB;
        int k0 = kt << 5;
#pragma unroll
        for (int it = 0; it < 4; it++) {
            int id = it * 256 + tid;
            int hl = id >> 9, rid = id & 511;
            int row = rid >> 2, c = rid & 3;
            const bf16* src = (hl ? Alb : Ahb) + (size_t)row * K + k0 + c * 8;
            cp16(base + hl * ATILE + row * AROWB + c * 16, src);
        }
        if (TBK) {
#pragma unroll
            for (int it = 0; it < 4; it++) {
                int id = it * 256 + tid;
                int hl = id >> 9, rid = id & 511;
                int row = rid >> 2, c = rid & 3;
                const bf16* src = (hl ? Blb : Bhb) + (size_t)row * K + k0 + c * 8;
                cp16(base + ASTG + hl * ATILE + row * AROWB + c * 16, src);
            }
        } else {
#pragma unroll
            for (int it = 0; it < 4; it++) {
                int id = it * 256 + tid;
                int hl = id >> 9, rid = id & 511;
                int k = rid >> 4, c = rid & 15;
                const bf16* src = (hl ? Blb : Bhb) + (size_t)(k0 + k) * N + c * 8;
                cp16(base + ASTG + hl * 8192 + k * 256 + ((c ^ (k & 7)) << 4), src);
            }
        }
        CP_COMMIT();
    };

    load_stage(0, 0);
    load_stage(1, 1);
    load_stage(2, 2);

    for (int kt = 0; kt < nch; kt++) {
        CP_WAIT2();
        __syncthreads();
        uint32_t aB = smb + (uint32_t)(kt & 3) * SB;
        uint32_t bB = aB + ASTG;

#pragma unroll
        for (int kh = 0; kh < 2; kh++) {
            uint32_t ahi[4][4], alo[4][4], bhi[4][2], blo[4][2];
            {
                int arow = wm + (lane & 15);
                uint32_t aoff = (uint32_t)(kh * 32 + ((lane >> 4) << 4));
#pragma unroll
                for (int i = 0; i < 4; i++) {
                    uint32_t ro = (uint32_t)(arow + i * 16) * AROWB + aoff;
                    ldmx4(ahi[i], aB + ro);
                    ldmx4(alo[i], aB + ATILE + ro);
                }
            }
            if (TBK) {
                int brow = wn + (lane & 7);
                uint32_t boff = (uint32_t)(kh * 32 + (((lane >> 3) & 1) << 4));
#pragma unroll
                for (int j = 0; j < 4; j++) {
                    uint32_t ro = (uint32_t)(brow + j * 8) * AROWB + boff;
                    ldmx2(bhi[j], bB + ro);
                    ldmx2(blo[j], bB + ATILE + ro);
                }
            } else {
                int kl = kh * 16 + (lane & 7) + ((lane >> 3) & 1) * 8;
                uint32_t kro = (uint32_t)kl << 8;
                int cbase = wn >> 3;
#pragma unroll
                for (int j = 0; j < 4; j++) {
                    uint32_t c2 = (uint32_t)((cbase + j) ^ (kl & 7)) << 4;
                    ldmx2t(bhi[j], bB + kro + c2);
                    ldmx2t(blo[j], bB + 8192 + kro + c2);
                }
            }
#pragma unroll
            for (int i = 0; i < 4; i++)
#pragma unroll
                for (int j = 0; j < 4; j++)
                    mma_bf16(acc[i][j], ahi[i], bhi[j]);
#pragma unroll
            for (int i = 0; i < 4; i++)
#pragma unroll
                for (int j = 0; j < 4; j++)
                    mma_bf16(acc[i][j], ahi[i], blo[j]);
#pragma unroll
            for (int i = 0; i < 4; i++)
#pragma unroll
                for (int j = 0; j < 4; j++)
                    mma_bf16(acc[i][j], alo[i], bhi[j]);
        }

        if (kt + 3 < nch) load_stage(kt + 3, (kt + 3) & 3);
        else CP_COMMIT();
    }

    // ---- epilogue ----
#pragma unroll
    for (int i = 0; i < 4; i++) {
        int r0 = bm + wm + i * 16 + (lane >> 2);
        int r1 = r0 + 8;
#pragma unroll
        for (int j = 0; j < 4; j++) {
            int gc = bn + wn + j * 8 + (lane & 3) * 2;
            float2 v0 = make_float2(acc[i][j][0], acc[i][j][1]);
            float2 v1 = make_float2(acc[i][j][2], acc[i][j][3]);
            if (bias) {
                float2 bv = *reinterpret_cast<const float2*>(bias + gc);
                v0.x += bv.x; v0.y += bv.y;
                v1.x += bv.x; v1.y += bv.y;
            }
            if (Rb) {
                float2 q0 = *reinterpret_cast<const float2*>(Rb + (size_t)r0 * ldc + gc);
                float2 q1 = *reinterpret_cast<const float2*>(Rb + (size_t)r1 * ldc + gc);
                v0.x += q0.x; v0.y += q0.y;
                v1.x += q1.x; v1.y += q1.y;
            }
            if (relu_flag) {
                v0.x = fmaxf(v0.x, 0.f); v0.y = fmaxf(v0.y, 0.f);
                v1.x = fmaxf(v1.x, 0.f); v1.y = fmaxf(v1.y, 0.f);
            }
            if (Cb) {
                *reinterpret_cast<float2*>(Cb + (size_t)r0 * ldc + gc) = v0;
                *reinterpret_cast<float2*>(Cb + (size_t)r1 * ldc + gc) = v1;
            }
            if (Chb) {
                uint32_t h0, l0, h1, l1;
                split2(v0.x, v0.y, h0, l0);
                split2(v1.x, v1.y, h1, l1);
                *reinterpret_cast<uint32_t*>(Chb + (size_t)r0 * ldc + gc) = h0;
                *reinterpret_cast<uint32_t*>(Clb + (size_t)r0 * ldc + gc) = l0;
                *reinterpret_cast<uint32_t*>(Chb + (size_t)r1 * ldc + gc) = h1;
                *reinterpret_cast<uint32_t*>(Clb + (size_t)r1 * ldc + gc) = l1;
            }
        }
    }
}

// ====================== elementwise kernels ======================
__global__ void split_k(const float* __restrict__ s, bf16* __restrict__ h,
                        bf16* __restrict__ l, size_t n4)
{
    for (size_t i = (size_t)blockIdx.x * blockDim.x + threadIdx.x; i < n4;
         i += (size_t)gridDim.x * blockDim.x) {
        float4 v = reinterpret_cast<const float4*>(s)[i];
        uint32_t h0, l0, h1, l1;
        split2(v.x, v.y, h0, l0);
        split2(v.z, v.w, h1, l1);
        reinterpret_cast<uint2*>(h)[i] = make_uint2(h0, h1);
        reinterpret_cast<uint2*>(l)[i] = make_uint2(l0, l1);
    }
}

__global__ void zero_k(uint4* __restrict__ p, size_t n16)
{
    for (size_t i = (size_t)blockIdx.x * blockDim.x + threadIdx.x; i < n16;
         i += (size_t)gridDim.x * blockDim.x)
        p[i] = make_uint4(0, 0, 0, 0);
}

__global__ void padsplit_k(const float* __restrict__ src, bf16* __restrict__ h,
                           bf16* __restrict__ l, int K, int Nsrc, int col0)
{
    int total = K * Nsrc;
    for (int i = blockIdx.x * blockDim.x + threadIdx.x; i < total;
         i += gridDim.x * blockDim.x) {
        int k = i / Nsrc, n = i - k * Nsrc;
        float v = src[i];
        uint32_t u = __float_as_uint(v);
        float lv = v - __uint_as_float(u & 0xFFFF0000u);
        size_t d = (size_t)k * 128 + col0 + n;
        reinterpret_cast<unsigned short*>(h)[d] = (unsigned short)(u >> 16);
        reinterpret_cast<unsigned short*>(l)[d] = (unsigned short)(pack_bf16x2(lv, lv) & 0xFFFFu);
    }
}

__global__ void norms_k(const float* __restrict__ G, float* __restrict__ nrm)
{
    int i = blockIdx.x * blockDim.x + threadIdx.x;
    if (i < BQ * PP) {
        int b = i >> 10, p = i & (PP - 1);
        nrm[i] = sqrtf(G[((size_t)b * PP + p) * PP + p]);
    }
}

// mirror upper->lower for symmetric gram buffers (32x32 smem tile transpose)
__global__ __launch_bounds__(256)
void mirror_k(float* __restrict__ A, float* __restrict__ B)
{
    int tj = blockIdx.x, ti = blockIdx.y, b = blockIdx.z;
    if (ti <= tj || (ti >> 2) == (tj >> 2)) return;   // only cross-128-block lower tiles
    __shared__ float ta[32][33], tb[32][33];
    int tx = threadIdx.x & 31, ty = threadIdx.x >> 5;
    size_t base = (size_t)b * PP * PP;
    // source tile (rows tj*32.., cols ti*32..) = upper; dest transposed
#pragma unroll
    for (int it = 0; it < 4; it++) {
        int r = ty + it * 8;
        size_t src = base + (size_t)(tj * 32 + r) * PP + ti * 32 + tx;
        ta[r][tx] = A[src];
        tb[r][tx] = B[src];
    }
    __syncthreads();
#pragma unroll
    for (int it = 0; it < 4; it++) {
        int r = ty + it * 8;
        size_t dst = base + (size_t)(ti * 32 + r) * PP + tj * 32 + tx;
        A[dst] = ta[tx][r];
        B[dst] = tb[tx][r];
    }
}

// head partial reduction: out[row, col] over K-slices + bias, 81-col scatter
__global__ void redheads_k(const float* __restrict__ hp1, const float* __restrict__ hp2,
                           const float* __restrict__ fab, const float* __restrict__ fcb,
                           const float* __restrict__ frb, float* __restrict__ out)
{
    int i = blockIdx.x * blockDim.x + threadIdx.x;
    int total = BQ * PP * 81;
    if (i >= total) return;
    int row = i / 81, col = i - row * 81;
    float v;
    if (col < 21) {
        v = fab[col];
#pragma unroll
        for (int s = 0; s < 2; s++)
            v += hp1[((size_t)s * BQ * PP + row) * 128 + col];
    } else {
        int c2 = col - 21;
        v = (c2 < 20) ? fcb[c2] : frb[c2 - 20];
#pragma unroll
        for (int s = 0; s < 4; s++)
            v += hp2[((size_t)s * BQ * PP + row) * 128 + c2];
    }
    out[i] = v;
}

// ---------------- graph construction (one warp per row; inline cos-normalization) ----
__device__ __forceinline__ void warp_argmin(float& v, int& l)
{
#pragma unroll
    for (int off = 16; off; off >>= 1) {
        float ov = __shfl_down_sync(0xffffffffu, v, off);
        int ol = __shfl_down_sync(0xffffffffu, l, off);
        if (ov < v) { v = ov; l = ol; }
    }
    v = __shfl_sync(0xffffffffu, v, 0);
    l = __shfl_sync(0xffffffffu, l, 0);
}
__device__ __forceinline__ void warp_argmax(float& v, int& l)
{
#pragma unroll
    for (int off = 16; off; off >>= 1) {
        float ov = __shfl_down_sync(0xffffffffu, v, off);
        int ol = __shfl_down_sync(0xffffffffu, l, off);
        if (ov > v) { v = ov; l = ol; }
    }
    v = __shfl_sync(0xffffffffu, v, 0);
    l = __shfl_sync(0xffffffffu, l, 0);
}

__global__ __launch_bounds__(128)
void build_adj_k(const float* __restrict__ iou, const float* __restrict__ dis,
                 const float* __restrict__ acos_, const float* __restrict__ ccos_,
                 const float* __restrict__ na, const float* __restrict__ nc,
                 const int* __restrict__ props,
                 bf16* __restrict__ awh, bf16* __restrict__ awl,
                 bf16* __restrict__ cwh, bf16* __restrict__ cwl)
{
    __shared__ float sio[4][PP];
    int warp = threadIdx.x >> 5, lane = threadIdx.x & 31;
    int row = blockIdx.x * 4 + warp;
    if (row >= BQ * PP) return;
    int b = row >> 10;
    int p = row & (PP - 1);
    const float* iour = iou + (size_t)row * PP;
    const float* disr = dis + (size_t)row * PP;
    const float* ar = acos_ + (size_t)row * PP;
    const float* cr = ccos_ + (size_t)row * PP;
    const float* nab = na + (b << 10);
    const float* ncb = nc + (b << 10);
    float npa = nab[p], npc = ncb[p];
    int pn = props[b];
    bool pv = p < pn;

    float* io_s = sio[warp];
    for (int q = lane; q < PP; q += 32) io_s[q] = iour[q];
    __syncwarp();

    float dv[6]; int di[6];
#pragma unroll
    for (int j = 0; j < 6; j++) { dv[j] = 3.0e38f; di[j] = -1; }
    float sv[2] = {-3.0e38f, -3.0e38f};
    int si[2] = {-1, -1};

    for (int q = lane; q < PP; q += 32) {
        float io = io_s[q];
        bool ip = io > 0.0f;
        bool qv = q < pn;
        bool v2 = pv && qv;

        float dm = v2 ? (ip ? 2.0f : disr[q]) : 1.0e9f;
        if (dm < dv[5]) {
            dv[5] = dm; di[5] = q;
#pragma unroll
            for (int j = 5; j > 0; j--) {
                if (dv[j] < dv[j - 1]) {
                    float tv = dv[j]; dv[j] = dv[j - 1]; dv[j - 1] = tv;
                    int ti = di[j]; di[j] = di[j - 1]; di[j - 1] = ti;
                }
            }
        }
        float av = ar[q] / (npa * nab[q] + 1e-6f);
        float sm = v2 ? (ip ? 0.0f : (av - (q == p ? 1.0f : 0.0f))) : -1.0e9f;
        if (sm > sv[1]) {
            if (sm > sv[0]) { sv[1] = sv[0]; si[1] = si[0]; sv[0] = sm; si[0] = q; }
            else            { sv[1] = sm; si[1] = q; }
        }
    }

    int sel[8];
    {
        int ptr = 0;
        for (int k = 0; k < 6; k++) {
            float cv = (ptr < 6) ? dv[ptr] : 3.0e38f;
            int ci = (ptr < 6) ? di[ptr] : -1;
            float v = cv; int l = lane;
            warp_argmin(v, l);
            sel[k] = __shfl_sync(0xffffffffu, ci, l);
            if (lane == l) ptr++;
        }
    }
    {
        int ptr = 0;
        for (int k = 0; k < 2; k++) {
            float cv = (ptr < 2) ? sv[ptr] : -3.0e38f;
            int ci = (ptr < 2) ? si[ptr] : -1;
            float v = cv; int l = lane;
            warp_argmax(v, l);
            sel[6 + k] = __shfl_sync(0xffffffffu, ci, l);
            if (lane == l) ptr++;
        }
    }
#pragma unroll
    for (int k = 0; k < 8; k++) {
        int q = sel[k];
        bool ok = (q >= 0) && pv && (q < pn) && !(io_s[q] > 0.0f);
        sel[k] = ok ? q : -1;
    }

    unsigned mbits = 0;
    for (int i = 0; i < 32; i++) {
        int q = lane + 32 * i;
        float io = io_s[q];
        bool bit = (q != p) && (io > 0.7f);
#pragma unroll
        for (int k = 0; k < 8; k++) bit |= (sel[k] == q);
        mbits |= (bit ? 1u : 0u) << i;
    }
    int cnt = __popc(mbits);
#pragma unroll
    for (int off = 16; off; off >>= 1) cnt += __shfl_xor_sync(0xffffffffu, cnt, off);
    float inv = 1.0f / ((float)cnt + 1e-6f);

    unsigned short* ah_ = reinterpret_cast<unsigned short*>(awh) + (size_t)row * PP;
    unsigned short* al_ = reinterpret_cast<unsigned short*>(awl) + (size_t)row * PP;
    unsigned short* ch_ = reinterpret_cast<unsigned short*>(cwh) + (size_t)row * PP;
    unsigned short* cl_ = reinterpret_cast<unsigned short*>(cwl) + (size_t)row * PP;
    for (int i = 0; i < 32; i++) {
        int q = lane + 32 * i;
        float m = ((mbits >> i) & 1u) ? inv : 0.0f;
        if (q == p) m += 1.0f;
        float av = ar[q] / (npa * nab[q] + 1e-6f);
        float cv = cr[q] / (npc * ncb[q] + 1e-6f);
        float a = fmaxf(av * m, 0.f);
        float c = fmaxf(cv * m, 0.f);
        uint32_t ua = __float_as_uint(a);
        uint32_t uc = __float_as_uint(c);
        float la = a - __uint_as_float(ua & 0xFFFF0000u);
        float lc = c - __uint_as_float(uc & 0xFFFF0000u);
        ah_[q] = (unsigned short)(ua >> 16);
        al_[q] = (unsigned short)(pack_bf16x2(la, la) & 0xFFFFu);
        ch_[q] = (unsigned short)(uc >> 16);
        cl_[q] = (unsigned short)(pack_bf16x2(lc, lc) & 0xFFFFu);
    }
}

// ---------------- host orchestration ----------------
static void gx(int tbk, const bf16* Ah, const bf16* Al, const bf16* Bh, const bf16* Bl,
               float* C, bf16* Ch, bf16* Cl,
               int M, int N, int K, int Klen, int symm,
               long sA, long sB, long sC, int batch,
               const float* bias, const float* resid, long sR,
               int ldc, int relu)
{
    int smem = NSTAGE * (ASTG + (tbk ? BSTG1 : BSTG0));
    dim3 grid(Klen ? K / Klen : N / 128, M / 128, batch);
    if (tbk) {
        cudaFuncSetAttribute(gemmx_k<1>, cudaFuncAttributeMaxDynamicSharedMemorySize, smem);
        gemmx_k<1><<<grid, 256, smem>>>(Ah, Al, Bh, Bl, C, Ch, Cl, N, K, Klen, symm,
                                        sA, sB, sC, bias, resid, sR, ldc, relu);
    } else {
        cudaFuncSetAttribute(gemmx_k<0>, cudaFuncAttributeMaxDynamicSharedMemorySize, smem);
        gemmx_k<0><<<grid, 256, smem>>>(Ah, Al, Bh, Bl, C, Ch, Cl, N, K, Klen, symm,
                                        sA, sB, sC, bias, resid, sR, ldc, relu);
    }
}

#define SYM(var, sym) cudaGetSymbolAddress((void**)&var, sym)

extern "C" void kernel_launch(void* const* d_in, const int* in_sizes, int n_in,
                              void* d_out, int out_size)
{
    const float* act   = (const float*)d_in[0];
    const float* comp  = (const float*)d_in[1];
    const float* iou   = (const float*)d_in[2];
    const float* dis   = (const float*)d_in[3];
    const int*   props = (const int*)d_in[4];
    const float* a_w1  = (const float*)d_in[5];
    const float* a_b1  = (const float*)d_in[6];
    const float* a_w2  = (const float*)d_in[7];
    const float* a_b2  = (const float*)d_in[8];
    const float* c_w1  = (const float*)d_in[9];
    const float* c_b1  = (const float*)d_in[10];
    const float* c_w2  = (const float*)d_in[11];
    const float* c_b2  = (const float*)d_in[12];
    const float* fa_w  = (const float*)d_in[13];
    const float* fa_b  = (const float*)d_in[14];
    const float* fc_w  = (const float*)d_in[15];
    const float* fc_b  = (const float*)d_in[16];
    const float* fr_w  = (const float*)d_in[17];
    const float* fr_b  = (const float*)d_in[18];
    float* out = (float*)d_out;

    float *acos_, *ccos_, *na, *nc, *hp1, *hp2;
    bf16 *ah, *al, *ch_, *cl_, *aadjh, *aadjl, *cadjh, *cadjl;
    bf16 *w1ah, *w1al, *w2ah, *w2al, *w1ch, *w1cl, *w2ch, *w2cl;
    bf16 *t1h, *t1l, *t2h, *t2l, *t3h, *t3l, *ofah, *ofal, *ofch, *ofcl;
    bf16 *wp1h, *wp1l, *wp2h, *wp2l;
    SYM(acos_, g_acos); SYM(ccos_, g_ccos); SYM(na, g_na); SYM(nc, g_nc);
    SYM(ah, g_ah); SYM(al, g_al); SYM(ch_, g_ch); SYM(cl_, g_cl);
    SYM(aadjh, g_aadjh); SYM(aadjl, g_aadjl); SYM(cadjh, g_cadjh); SYM(cadjl, g_cadjl);
    SYM(w1ah, g_w1ah); SYM(w1al, g_w1al); SYM(w2ah, g_w2ah); SYM(w2al, g_w2al);
    SYM(w1ch, g_w1ch); SYM(w1cl, g_w1cl); SYM(w2ch, g_w2ch); SYM(w2cl, g_w2cl);
    SYM(t1h, g_t1h); SYM(t1l, g_t1l); SYM(t2h, g_t2h); SYM(t2l, g_t2l);
    SYM(t3h, g_t3h); SYM(t3l, g_t3l);
    SYM(ofah, g_ofah); SYM(ofal, g_ofal); SYM(ofch, g_ofch); SYM(ofcl, g_ofcl);
    SYM(wp1h, g_wp1h); SYM(wp1l, g_wp1l); SYM(wp2h, g_wp2h); SYM(wp2l, g_wp2l);
    SYM(hp1, g_hp1); SYM(hp2, g_hp2);

    // 0) split inputs + weights to bf16 hi/lo
    split_k<<<1024, 256>>>(act, ah, al, (size_t)BQ * PP * DDA / 4);
    split_k<<<2048, 256>>>(comp, ch_, cl_, (size_t)BQ * PP * DDC / 4);
    split_k<<<256, 256>>>(a_w1, w1ah, w1al, (size_t)DDA * HID / 4);
    split_k<<<256, 256>>>(a_w2, w2ah, w2al, (size_t)HID * DDA / 4);
    split_k<<<512, 256>>>(c_w1, w1ch, w1cl, (size_t)DDC * HID / 4);
    split_k<<<512, 256>>>(c_w2, w2ch, w2cl, (size_t)HID * DDC / 4);

    zero_k<<<64, 256>>>((uint4*)wp1h, (size_t)DDA * 128 * 2 / 16);
    zero_k<<<64, 256>>>((uint4*)wp1l, (size_t)DDA * 128 * 2 / 16);
    zero_k<<<128, 256>>>((uint4*)wp2h, (size_t)DDC * 128 * 2 / 16);
    zero_k<<<128, 256>>>((uint4*)wp2l, (size_t)DDC * 128 * 2 / 16);
    padsplit_k<<<128, 256>>>(fa_w, wp1h, wp1l, DDA, 21, 0);
    padsplit_k<<<256, 256>>>(fc_w, wp2h, wp2l, DDC, 20, 0);
    padsplit_k<<<512, 256>>>(fr_w, wp2h, wp2l, DDC, 40, 20);

    // 1) Gram matrices, symmetric (upper blocks only) + mirror
    gx(1, ah, al, ah, al, acos_, 0, 0, PP, PP, DDA, 0, 1,
       (long)PP * DDA, (long)PP * DDA, (long)PP * PP, BQ, 0, 0, 0, PP, 0);
    gx(1, ch_, cl_, ch_, cl_, ccos_, 0, 0, PP, PP, DDC, 0, 1,
       (long)PP * DDC, (long)PP * DDC, (long)PP * PP, BQ, 0, 0, 0, PP, 0);
    mirror_k<<<dim3(32, 32, BQ), 256>>>(acos_, ccos_);

    // 2) norms (raw gram diag)
    norms_k<<<(BQ * PP + 255) / 256, 256>>>(acos_, na);
    norms_k<<<(BQ * PP + 255) / 256, 256>>>(ccos_, nc);

    // 3) graph construction (normalization fused)
    build_adj_k<<<BQ * PP / 4, 128>>>(iou, dis, acos_, ccos_, na, nc, props,
                                      aadjh, aadjl, cadjh, cadjl);

    // 4) Act GCN chain
    gx(0, ah, al, w1ah, w1al, 0, t1h, t1l, BQ * PP, HID, DDA, 0, 0,
       0, 0, 0, 1, 0, 0, 0, HID, 0);
    gx(0, aadjh, aadjl, t1h, t1l, 0, t2h, t2l, PP, HID, PP, 0, 0,
       (long)PP * PP, (long)PP * HID, (long)PP * HID, BQ, a_b1, 0, 0, HID, 1);
    gx(0, t2h, t2l, w2ah, w2al, 0, t3h, t3l, BQ * PP, DDA, HID, 0, 0,
       0, 0, 0, 1, 0, 0, 0, DDA, 0);
    gx(0, aadjh, aadjl, t3h, t3l, 0, ofah, ofal, PP, DDA, PP, 0, 0,
       (long)PP * PP, (long)PP * DDA, (long)PP * DDA, BQ,
       a_b2, act, (long)PP * DDA, DDA, 0);
    // act head partials: 2 K-slices of 512
    gx(0, ofah, ofal, wp1h, wp1l, hp1, 0, 0, BQ * PP, 128, DDA, 512, 0,
       0, 0, (long)BQ * PP * 128, 1, 0, 0, 0, 128, 0);

    // 5) Comp GCN chain
    gx(0, ch_, cl_, w1ch, w1cl, 0, t1h, t1l, BQ * PP, HID, DDC, 0, 0,
       0, 0, 0, 1, 0, 0, 0, HID, 0);
    gx(0, cadjh, cadjl, t1h, t1l, 0, t2h, t2l, PP, HID, PP, 0, 0,
       (long)PP * PP, (long)PP * HID, (long)PP * HID, BQ, c_b1, 0, 0, HID, 1);
    gx(0, t2h, t2l, w2ch, w2cl, 0, t3h, t3l, BQ * PP, DDC, HID, 0, 0,
       0, 0, 0, 1, 0, 0, 0, DDC, 0);
    gx(0, cadjh, cadjl, t3h, t3l, 0, ofch, ofcl, PP, DDC, PP, 0, 0,
       (long)PP * PP, (long)PP * DDC, (long)PP * DDC, BQ,
       c_b2, comp, (long)PP * DDC, DDC, 0);
    // comp head partials: 4 K-slices of 768
    gx(0, ofch, ofcl, wp2h, wp2l, hp2, 0, 0, BQ * PP, 128, DDC, 768, 0,
       0, 0, (long)BQ * PP * 128, 1, 0, 0, 0, 128, 0);

    // 6) head reduction -> out
    redheads_k<<<(BQ * PP * 81 + 255) / 256, 256>>>(hp1, hp2, fa_b, fc_b, fr_b, out);
}